// round 2
// baseline (speedup 1.0000x reference)
#include <cuda_runtime.h>
#include <cstdint>
#include <cstddef>

#define BB 4
#define TT 1024
#define HH 16
#define DD 64
#define CC 1024
#define MM 4096
#define NREL 1999

__device__ float g_Q[(size_t)BB * HH * TT * DD];
__device__ float g_K[(size_t)BB * HH * TT * DD];
__device__ float g_V[(size_t)BB * HH * TT * DD];
__device__ float g_S[(size_t)BB * HH * TT * TT];
__device__ float g_O[(size_t)MM * CC];
__device__ int   g_mask_flags;

__global__ void mask_detect_kernel(const unsigned int* __restrict__ m) {
    unsigned f = 0;
    for (unsigned i = blockIdx.x * blockDim.x + threadIdx.x; i < (1u << 20);
         i += blockDim.x * gridDim.x) {
        unsigned w = m[i];
        if (w == 0u) continue;
        unsigned lo = w & 0xFFFFu;
        if (lo == 0x3F80u || lo == 0x3C00u) f |= 1u;          // bf16 / f16
        if (((w & 0xFEFEFEFEu) == 0u) && w > 1u) f |= 2u;     // uint8
    }
    if (f) atomicOr(&g_mask_flags, (int)f);
}

// C = A(4096x1024) * W(1024x1024)^T + bias.
// srcsel: 0 -> use extA, 1 -> use g_O as A.
// dstsel: 0 g_Q, 1 g_K, 2 g_V, 3 extDst.
// headmode: 1 -> scatter to [bh][t][d]; 0 -> plain row-major.
__global__ void __launch_bounds__(256) gemm_kernel(
    const float* __restrict__ extA, const float* __restrict__ W,
    const float* __restrict__ bias, float* extDst, int srcsel, int dstsel,
    int headmode)
{
    __shared__ __align__(16) float As[8][128];
    __shared__ __align__(16) float Bs[8][128];
    const float* A = srcsel ? g_O : extA;
    float* Cout = (dstsel == 0) ? g_Q : (dstsel == 1) ? g_K :
                  (dstsel == 2) ? g_V : extDst;

    const int tx = threadIdx.x;
    const int bm = blockIdx.y * 128;
    const int bn = blockIdx.x * 128;
    const int lr = tx >> 1;
    const int lc = (tx & 1) << 2;
    const int tm = (tx >> 4) << 3;
    const int tn = (tx & 15) << 3;

    const float* Ap = A + (size_t)(bm + lr) * 1024 + lc;
    const float* Wp = W + (size_t)(bn + lr) * 1024 + lc;

    float acc[8][8];
#pragma unroll
    for (int i = 0; i < 8; i++)
#pragma unroll
        for (int j = 0; j < 8; j++) acc[i][j] = 0.f;

    for (int k0 = 0; k0 < 1024; k0 += 8) {
        float4 av = *(const float4*)(Ap + k0);
        float4 wv = *(const float4*)(Wp + k0);
        __syncthreads();
        As[lc + 0][lr] = av.x; As[lc + 1][lr] = av.y;
        As[lc + 2][lr] = av.z; As[lc + 3][lr] = av.w;
        Bs[lc + 0][lr] = wv.x; Bs[lc + 1][lr] = wv.y;
        Bs[lc + 2][lr] = wv.z; Bs[lc + 3][lr] = wv.w;
        __syncthreads();
#pragma unroll
        for (int kk = 0; kk < 8; kk++) {
            float4 a0 = *(const float4*)&As[kk][tm];
            float4 a1 = *(const float4*)&As[kk][tm + 4];
            float4 b0 = *(const float4*)&Bs[kk][tn];
            float4 b1 = *(const float4*)&Bs[kk][tn + 4];
            float a[8]  = {a0.x, a0.y, a0.z, a0.w, a1.x, a1.y, a1.z, a1.w};
            float bb[8] = {b0.x, b0.y, b0.z, b0.w, b1.x, b1.y, b1.z, b1.w};
#pragma unroll
            for (int i = 0; i < 8; i++)
#pragma unroll
                for (int j = 0; j < 8; j++)
                    acc[i][j] = fmaf(a[i], bb[j], acc[i][j]);
        }
    }

#pragma unroll
    for (int i = 0; i < 8; i++) {
        const int m = bm + tm + i;
#pragma unroll
        for (int j = 0; j < 8; j++) {
            const int n = bn + tn + j;
            const float v = acc[i][j] + bias[n];
            size_t idx;
            if (headmode) {
                idx = (((size_t)((m >> 10) * 16 + (n >> 6)) * 1024 +
                        (size_t)(m & 1023)) << 6) + (n & 63);
            } else {
                idx = (size_t)m * 1024 + n;
            }
            Cout[idx] = v;
        }
    }
}

// S[bh][q][k] = 8 * ( Q.K + rawq . rel_emb[clip(k-q+999,0,1998)] )
__global__ void __launch_bounds__(256) logits_kernel(
    const float* __restrict__ rawq, const float* __restrict__ relE)
{
    __shared__ __align__(16) float Qs[32][64];
    __shared__ __align__(16) float Ks[32][64];
    __shared__ __align__(16) float Rs[32][64];
    __shared__ __align__(16) float Es[32][128];

    const int tx = threadIdx.x;
    const int kt = blockIdx.x, qt = blockIdx.y, bh = blockIdx.z;
    const int b = bh >> 4, h = bh & 15;
    const int q0 = qt << 6, k0 = kt << 6;
    const int base = k0 - q0 + 999;
    const int tm = (tx >> 4) << 2;
    const int tn = (tx & 15) << 2;

    const float* Qb = g_Q + ((size_t)bh * 1024 + q0) * 64;
    const float* Kb = g_K + ((size_t)bh * 1024 + k0) * 64;
    const float* Rb = rawq + ((size_t)(b * 1024 + q0)) * 1024 + h * 64;

    float acc[4][4];
#pragma unroll
    for (int i = 0; i < 4; i++)
#pragma unroll
        for (int j = 0; j < 4; j++) acc[i][j] = 0.f;

    for (int d0 = 0; d0 < 64; d0 += 32) {
        __syncthreads();
#pragma unroll
        for (int it = 0; it < 2; it++) {
            const int idx = tx + (it << 8);
            const int qq = idx >> 3;
            const int c4 = (idx & 7) << 2;
            float4 qv = *(const float4*)(Qb + (size_t)qq * 64 + d0 + c4);
            Qs[c4 + 0][qq] = qv.x; Qs[c4 + 1][qq] = qv.y;
            Qs[c4 + 2][qq] = qv.z; Qs[c4 + 3][qq] = qv.w;
            float4 kv = *(const float4*)(Kb + (size_t)qq * 64 + d0 + c4);
            Ks[c4 + 0][qq] = kv.x; Ks[c4 + 1][qq] = kv.y;
            Ks[c4 + 2][qq] = kv.z; Ks[c4 + 3][qq] = kv.w;
            float4 rv = *(const float4*)(Rb + (size_t)qq * 1024 + d0 + c4);
            Rs[c4 + 0][qq] = rv.x; Rs[c4 + 1][qq] = rv.y;
            Rs[c4 + 2][qq] = rv.z; Rs[c4 + 3][qq] = rv.w;
        }
        for (int idx = tx; idx < 127 * 8; idx += 256) {
            const int ls = idx >> 3;
            const int c4 = (idx & 7) << 2;
            int j = base + ls - 63;
            j = j < 0 ? 0 : (j > 1998 ? 1998 : j);
            float4 ev = *(const float4*)(relE + (size_t)j * 64 + d0 + c4);
            Es[c4 + 0][ls] = ev.x; Es[c4 + 1][ls] = ev.y;
            Es[c4 + 2][ls] = ev.z; Es[c4 + 3][ls] = ev.w;
        }
        __syncthreads();

        const int eb = tn - tm + 60;
#pragma unroll 8
        for (int kk = 0; kk < 32; kk++) {
            float4 qv = *(const float4*)&Qs[kk][tm];
            float4 kv = *(const float4*)&Ks[kk][tn];
            float4 rv = *(const float4*)&Rs[kk][tm];
            const float* erow = &Es[kk][eb];
            float qa[4] = {qv.x, qv.y, qv.z, qv.w};
            float ka[4] = {kv.x, kv.y, kv.z, kv.w};
            float ra[4] = {rv.x, rv.y, rv.z, rv.w};
            float e[7];
#pragma unroll
            for (int t = 0; t < 7; t++) e[t] = erow[t];
#pragma unroll
            for (int i = 0; i < 4; i++)
#pragma unroll
                for (int j = 0; j < 4; j++)
                    acc[i][j] = fmaf(qa[i], ka[j],
                                     fmaf(ra[i], e[j - i + 3], acc[i][j]));
        }
    }

    float* Sb = g_S + ((size_t)bh * 1024 + q0 + tm) * 1024 + k0 + tn;
#pragma unroll
    for (int i = 0; i < 4; i++)
#pragma unroll
        for (int j = 0; j < 4; j++)
            Sb[(size_t)i * 1024 + j] = acc[i][j] * 8.0f;
}

__global__ void __launch_bounds__(256) softmax_kernel(const void* __restrict__ mask)
{
    const int row = blockIdx.x;
    const int q = row & 1023;
    const int bh = row >> 10;
    const int b = bh >> 4;
    float* Srow = g_S + (size_t)row * 1024;
    const size_t mb = ((size_t)(b << 10) + q) * 1024;
    const int tx = threadIdx.x;
    const int k = tx << 2;

    const int fl = g_mask_flags;
    const int wdt = (fl & 1) ? 2 : ((fl & 2) ? 1 : 4);

    float4 sv = *(const float4*)(Srow + k);
    float v[4] = {sv.x, sv.y, sv.z, sv.w};
    const float NEG = __int_as_float(0xff800000);

    if (wdt == 4) {
        const unsigned int* mp = (const unsigned int*)mask + mb + k;
#pragma unroll
        for (int i = 0; i < 4; i++) if (mp[i]) v[i] = NEG;
    } else if (wdt == 2) {
        const unsigned short* mp = (const unsigned short*)mask + mb + k;
#pragma unroll
        for (int i = 0; i < 4; i++) if (mp[i]) v[i] = NEG;
    } else {
        const unsigned char* mp = (const unsigned char*)mask + mb + k;
#pragma unroll
        for (int i = 0; i < 4; i++) if (mp[i]) v[i] = NEG;
    }

    float mx = fmaxf(fmaxf(v[0], v[1]), fmaxf(v[2], v[3]));
#pragma unroll
    for (int off = 16; off; off >>= 1)
        mx = fmaxf(mx, __shfl_xor_sync(0xffffffffu, mx, off));
    __shared__ float red[8];
    if ((tx & 31) == 0) red[tx >> 5] = mx;
    __syncthreads();
    float rmax = red[0];
#pragma unroll
    for (int i = 1; i < 8; i++) rmax = fmaxf(rmax, red[i]);

    float e[4], s = 0.f;
#pragma unroll
    for (int i = 0; i < 4; i++) { e[i] = expf(v[i] - rmax); s += e[i]; }
#pragma unroll
    for (int off = 16; off; off >>= 1)
        s += __shfl_xor_sync(0xffffffffu, s, off);
    __syncthreads();
    if ((tx & 31) == 0) red[tx >> 5] = s;
    __syncthreads();
    float rs = 0.f;
#pragma unroll
    for (int i = 0; i < 8; i++) rs += red[i];
    const float inv = 1.0f / rs;

    *(float4*)(Srow + k) = make_float4(e[0] * inv, e[1] * inv, e[2] * inv, e[3] * inv);
}

__global__ void __launch_bounds__(256) av_kernel()
{
    __shared__ __align__(16) float Ps[16][128];
    __shared__ __align__(16) float Vs[16][64];

    const int tx = threadIdx.x;
    const int qt = blockIdx.x;
    const int bh = blockIdx.y;
    const int b = bh >> 4, h = bh & 15;
    const int tm = (tx >> 4) << 3;
    const int tn = (tx & 15) << 2;

    const float* Pb = g_S + ((size_t)bh * 1024 + qt * 128) * 1024;
    const float* Vb = g_V + (size_t)bh * 1024 * 64;

    float acc[8][4];
#pragma unroll
    for (int i = 0; i < 8; i++)
#pragma unroll
        for (int j = 0; j < 4; j++) acc[i][j] = 0.f;

    for (int k0 = 0; k0 < 1024; k0 += 16) {
        __syncthreads();
#pragma unroll
        for (int it = 0; it < 2; it++) {
            const int idx = tx + (it << 8);
            const int qq = idx >> 2;
            const int c4 = (idx & 3) << 2;
            float4 pv = *(const float4*)(Pb + (size_t)qq * 1024 + k0 + c4);
            Ps[c4 + 0][qq] = pv.x; Ps[c4 + 1][qq] = pv.y;
            Ps[c4 + 2][qq] = pv.z; Ps[c4 + 3][qq] = pv.w;
        }
        {
            const int kk = tx >> 4;
            const int d4 = (tx & 15) << 2;
            *(float4*)&Vs[kk][d4] = *(const float4*)(Vb + (size_t)(k0 + kk) * 64 + d4);
        }
        __syncthreads();
#pragma unroll
        for (int kk = 0; kk < 16; kk++) {
            float4 a0 = *(const float4*)&Ps[kk][tm];
            float4 a1 = *(const float4*)&Ps[kk][tm + 4];
            float4 bv = *(const float4*)&Vs[kk][tn];
            float a[8]  = {a0.x, a0.y, a0.z, a0.w, a1.x, a1.y, a1.z, a1.w};
            float bb[4] = {bv.x, bv.y, bv.z, bv.w};
#pragma unroll
            for (int i = 0; i < 8; i++)
#pragma unroll
                for (int j = 0; j < 4; j++)
                    acc[i][j] = fmaf(a[i], bb[j], acc[i][j]);
        }
    }

    float* Ob = g_O + ((size_t)(b * 1024 + qt * 128 + tm)) * 1024 + h * 64 + tn;
#pragma unroll
    for (int i = 0; i < 8; i++)
#pragma unroll
        for (int j = 0; j < 4; j++)
            Ob[(size_t)i * 1024 + j] = acc[i][j];
}

extern "C" void kernel_launch(void* const* d_in, const int* in_sizes, int n_in,
                              void* d_out, int out_size)
{
    const float* query = (const float*)d_in[0];
    const float* key_i = (const float*)d_in[1];
    const float* value = (const float*)d_in[2];
    const void*  mask  = d_in[3];
    const float* q_w = (const float*)d_in[4];
    const float* q_b = (const float*)d_in[5];
    const float* k_w = (const float*)d_in[6];
    const float* k_b = (const float*)d_in[7];
    const float* v_w = (const float*)d_in[8];
    const float* v_b = (const float*)d_in[9];
    const float* o_w = (const float*)d_in[10];
    const float* o_b = (const float*)d_in[11];
    const float* relE = (const float*)d_in[12];
    float* out = (float*)d_out;

    dim3 gg(1024 / 128, 4096 / 128);

    gemm_kernel<<<gg, 256>>>(query, q_w, q_b, nullptr, 0, 0, 1);
    gemm_kernel<<<gg, 256>>>(key_i, k_w, k_b, nullptr, 0, 1, 1);
    gemm_kernel<<<gg, 256>>>(value, v_w, v_b, nullptr, 0, 2, 1);

    mask_detect_kernel<<<256, 256>>>((const unsigned int*)mask);

    logits_kernel<<<dim3(16, 16, 64), 256>>>(query, relE);
    softmax_kernel<<<65536, 256>>>(mask);
    av_kernel<<<dim3(8, 64), 256>>>();

    gemm_kernel<<<gg, 256>>>(nullptr, o_w, o_b, out, 1, 3, 0);
}

// round 4
// speedup vs baseline: 1.3259x; 1.3259x over previous
#include <cuda_runtime.h>
#include <cuda_bf16.h>
#include <cstdint>
#include <cstddef>

#define BB 4
#define TT 1024
#define HH 16
#define DD 64
#define CC 1024
#define MM 4096

__device__ float g_Q[(size_t)BB * HH * TT * DD];
__device__ float g_K[(size_t)BB * HH * TT * DD];
__device__ float g_V[(size_t)BB * HH * TT * DD];
__device__ float g_S[(size_t)BB * HH * TT * TT];
__device__ float g_O[(size_t)MM * CC];
__device__ int   g_mask_flags;

// ===========================================================================
// mask dtype-width detector (validated)
// ===========================================================================
__global__ void mask_detect_kernel(const unsigned int* __restrict__ m) {
    unsigned f = 0;
    for (unsigned i = blockIdx.x * blockDim.x + threadIdx.x; i < (1u << 20);
         i += blockDim.x * gridDim.x) {
        unsigned w = m[i];
        if (w == 0u) continue;
        unsigned lo = w & 0xFFFFu;
        if (lo == 0x3F80u || lo == 0x3C00u) f |= 1u;
        if (((w & 0xFEFEFEFEu) == 0u) && w > 1u) f |= 2u;
    }
    if (f) atomicOr(&g_mask_flags, (int)f);
}

// ===========================================================================
// HMMA bf16x3 GEMM: C(4096x1024) = A @ W^T + bias (fp32 in/out)
//   D += Ah*Bh + Ah*Bl + Al*Bh   (mma.sync m16n8k16, fp32 accum)
// CTA tile 128x128, K chunk 32, double-buffered SMEM in FRAGMENT ORDER.
// 8 warps: warp (wm,wn) owns rows wm*64..+63, cols wn*32..+31.
// srcsel: 0 extA, 1 g_O.  dstsel: 0 g_Q, 1 g_K, 2 g_V, 3 extDst.
// headmode: 1 -> scatter [bh][t][d]; 0 -> row-major.
// ===========================================================================
#define CHUNK_U32 2048                     // 8KB per region (per chunk)
#define BUF_U32   (4 * CHUNK_U32)          // Ah, Al, Bh, Bl
#define SMEM_U32  (2 * BUF_U32)            // double buffer = 64KB

__device__ __forceinline__ void mma16816(float* c, const uint32_t* a,
                                         const uint32_t* b) {
    asm volatile(
        "mma.sync.aligned.m16n8k16.row.col.f32.bf16.bf16.f32 "
        "{%0,%1,%2,%3}, {%4,%5,%6,%7}, {%8,%9}, {%0,%1,%2,%3};"
        : "+f"(c[0]), "+f"(c[1]), "+f"(c[2]), "+f"(c[3])
        : "r"(a[0]), "r"(a[1]), "r"(a[2]), "r"(a[3]), "r"(b[0]), "r"(b[1]));
}

__device__ __forceinline__ void split2(float x, float y, uint32_t& hi, uint32_t& lo) {
    __nv_bfloat16 hx = __float2bfloat16(x);
    __nv_bfloat16 hy = __float2bfloat16(y);
    __nv_bfloat16 lx = __float2bfloat16(x - __bfloat162float(hx));
    __nv_bfloat16 ly = __float2bfloat16(y - __bfloat162float(hy));
    hi = ((uint32_t)__bfloat16_as_ushort(hy) << 16) | __bfloat16_as_ushort(hx);
    lo = ((uint32_t)__bfloat16_as_ushort(ly) << 16) | __bfloat16_as_ushort(lx);
}

// A-fragment u32 slot within an 8KB region (row 0..127, k 0..31 in chunk)
__device__ __forceinline__ int a_slot(int row, int k) {
    const int kstep = k >> 4, kk = k & 15;
    const int mt = row >> 4, rit = row & 15;
    const int lane = ((rit & 7) << 2) | ((kk >> 1) & 3);
    const int r = (rit >> 3) | (((kk >> 3) & 1) << 1);
    return (((kstep << 3) + mt) << 7) + (lane << 2) + r;   // ((ks*8+mt)*32+lane)*4+r
}
// B-fragment u32 slot (n 0..127, k 0..31)
__device__ __forceinline__ int b_slot(int n, int k) {
    const int kstep = k >> 4, kk = k & 15;
    const int nt = n >> 3, g = n & 7;
    const int lane = (g << 2) | ((kk >> 1) & 3);
    const int r = (kk >> 3) & 1;
    return (((kstep << 4) + nt) << 6) + (lane << 1) + r;   // ((ks*16+nt)*32+lane)*2+r
}

__global__ void __launch_bounds__(256, 1) mma_gemm_kernel(
    const float* __restrict__ extA, const float* __restrict__ W,
    const float* __restrict__ bias, float* extDst, int srcsel, int dstsel,
    int headmode)
{
    extern __shared__ __align__(16) uint32_t smem[];
    const int tid = threadIdx.x;
    const int wid = tid >> 5;
    const int lane = tid & 31;
    const int wm = wid >> 2;          // 0..1
    const int wn = wid & 3;           // 0..3
    const int g = lane >> 2;          // fragment group id
    const int tig = lane & 3;

    const float* A = srcsel ? g_O : extA;
    float* Cout = (dstsel == 0) ? g_Q : (dstsel == 1) ? g_K :
                  (dstsel == 2) ? g_V : extDst;
    const int bm = blockIdx.y << 7;
    const int bn = blockIdx.x << 7;

    // per-thread global-load coords: 4 float4 each for A and B
    const int lrow = tid >> 1;                 // 0..127
    const int lk0 = (tid & 1) << 4;            // 0 or 16 (chunk-local k base)
    const float* Agp = A + (size_t)(bm + lrow) * 1024 + lk0;
    const float* Bgp = W + (size_t)(bn + lrow) * 1024 + lk0;

    float acc[4][4][4];
#pragma unroll
    for (int i = 0; i < 4; i++)
#pragma unroll
        for (int j = 0; j < 4; j++)
#pragma unroll
            for (int r = 0; r < 4; r++) acc[i][j][r] = 0.f;

    float4 pa[4], pb[4];
#pragma unroll
    for (int q = 0; q < 4; q++) {
        pa[q] = *(const float4*)(Agp + (q << 2));
        pb[q] = *(const float4*)(Bgp + (q << 2));
    }

    // store chunk into buffer buf
    auto stage = [&](int buf) {
        uint32_t* Ah = smem + buf * BUF_U32;
        uint32_t* Al = Ah + CHUNK_U32;
        uint32_t* Bh = Al + CHUNK_U32;
        uint32_t* Bl = Bh + CHUNK_U32;
#pragma unroll
        for (int q = 0; q < 4; q++) {
            const int kq = lk0 + (q << 2);
            uint32_t h0, l0, h1, l1;
            split2(pa[q].x, pa[q].y, h0, l0);
            split2(pa[q].z, pa[q].w, h1, l1);
            int s0 = a_slot(lrow, kq), s1 = a_slot(lrow, kq + 2);
            Ah[s0] = h0; Al[s0] = l0; Ah[s1] = h1; Al[s1] = l1;
            split2(pb[q].x, pb[q].y, h0, l0);
            split2(pb[q].z, pb[q].w, h1, l1);
            s0 = b_slot(lrow, kq); s1 = b_slot(lrow, kq + 2);
            Bh[s0] = h0; Bl[s0] = l0; Bh[s1] = h1; Bl[s1] = l1;
        }
    };

    stage(0);
    __syncthreads();

#pragma unroll 1
    for (int s = 0; s < 32; s++) {
        if (s < 31) {
            const int koff = (s + 1) << 5;
#pragma unroll
            for (int q = 0; q < 4; q++) {
                pa[q] = *(const float4*)(Agp + koff + (q << 2));
                pb[q] = *(const float4*)(Bgp + koff + (q << 2));
            }
        }
        const uint32_t* Ah = smem + (s & 1) * BUF_U32;
        const uint32_t* Al = Ah + CHUNK_U32;
        const uint32_t* Bh = Al + CHUNK_U32;
        const uint32_t* Bl = Bh + CHUNK_U32;

#pragma unroll
        for (int ks = 0; ks < 2; ks++) {
            uint32_t bh[4][2], bl[4][2];
#pragma unroll
            for (int j = 0; j < 4; j++) {
                const int nt = (wn << 2) + j;
                const int bi = (((ks << 4) + nt) << 6) + (lane << 1);
                *(uint2*)bh[j] = *(const uint2*)(Bh + bi);
                *(uint2*)bl[j] = *(const uint2*)(Bl + bi);
            }
#pragma unroll
            for (int i = 0; i < 4; i++) {
                const int mt = (wm << 2) + i;
                const int ai = (((ks << 3) + mt) << 7) + (lane << 2);
                uint32_t ah[4], al[4];
                *(uint4*)ah = *(const uint4*)(Ah + ai);
                *(uint4*)al = *(const uint4*)(Al + ai);
#pragma unroll
                for (int j = 0; j < 4; j++) {
                    mma16816(acc[i][j], ah, bh[j]);
                    mma16816(acc[i][j], ah, bl[j]);
                    mma16816(acc[i][j], al, bh[j]);
                }
            }
        }
        __syncthreads();
        if (s < 31) stage((s + 1) & 1);
        __syncthreads();
    }

    // epilogue: acc[i][j] tile rows bm+wm*64+i*16+{g, g+8}, cols bn+wn*32+j*8+tig*2
#pragma unroll
    for (int i = 0; i < 4; i++) {
        const int m0 = bm + (wm << 6) + (i << 4) + g;
#pragma unroll
        for (int j = 0; j < 4; j++) {
            const int n = bn + (wn << 5) + (j << 3) + (tig << 1);
            const float2 bv = *(const float2*)(bias + n);
#pragma unroll
            for (int half = 0; half < 2; half++) {
                const int m = m0 + (half << 3);
                float2 o;
                o.x = acc[i][j][half * 2 + 0] + bv.x;
                o.y = acc[i][j][half * 2 + 1] + bv.y;
                size_t idx;
                if (headmode) {
                    idx = (((size_t)((m >> 10) * 16 + (n >> 6)) * 1024 +
                            (size_t)(m & 1023)) << 6) + (n & 63);
                } else {
                    idx = (size_t)m * 1024 + n;
                }
                *(float2*)(Cout + idx) = o;
            }
        }
    }
}

// ===========================================================================
// logits / softmax / av — unchanged (validated fp32 path)
// ===========================================================================
__global__ void __launch_bounds__(256) logits_kernel(
    const float* __restrict__ rawq, const float* __restrict__ relE)
{
    __shared__ __align__(16) float Qs[32][64];
    __shared__ __align__(16) float Ks[32][64];
    __shared__ __align__(16) float Rs[32][64];
    __shared__ __align__(16) float Es[32][128];

    const int tx = threadIdx.x;
    const int kt = blockIdx.x, qt = blockIdx.y, bh = blockIdx.z;
    const int b = bh >> 4, h = bh & 15;
    const int q0 = qt << 6, k0 = kt << 6;
    const int base = k0 - q0 + 999;
    const int tm = (tx >> 4) << 2;
    const int tn = (tx & 15) << 2;

    const float* Qb = g_Q + ((size_t)bh * 1024 + q0) * 64;
    const float* Kb = g_K + ((size_t)bh * 1024 + k0) * 64;
    const float* Rb = rawq + ((size_t)(b * 1024 + q0)) * 1024 + h * 64;

    float acc[4][4];
#pragma unroll
    for (int i = 0; i < 4; i++)
#pragma unroll
        for (int j = 0; j < 4; j++) acc[i][j] = 0.f;

    for (int d0 = 0; d0 < 64; d0 += 32) {
        __syncthreads();
#pragma unroll
        for (int it = 0; it < 2; it++) {
            const int idx = tx + (it << 8);
            const int qq = idx >> 3;
            const int c4 = (idx & 7) << 2;
            float4 qv = *(const float4*)(Qb + (size_t)qq * 64 + d0 + c4);
            Qs[c4 + 0][qq] = qv.x; Qs[c4 + 1][qq] = qv.y;
            Qs[c4 + 2][qq] = qv.z; Qs[c4 + 3][qq] = qv.w;
            float4 kv = *(const float4*)(Kb + (size_t)qq * 64 + d0 + c4);
            Ks[c4 + 0][qq] = kv.x; Ks[c4 + 1][qq] = kv.y;
            Ks[c4 + 2][qq] = kv.z; Ks[c4 + 3][qq] = kv.w;
            float4 rv = *(const float4*)(Rb + (size_t)qq * 1024 + d0 + c4);
            Rs[c4 + 0][qq] = rv.x; Rs[c4 + 1][qq] = rv.y;
            Rs[c4 + 2][qq] = rv.z; Rs[c4 + 3][qq] = rv.w;
        }
        for (int idx = tx; idx < 127 * 8; idx += 256) {
            const int ls = idx >> 3;
            const int c4 = (idx & 7) << 2;
            int j = base + ls - 63;
            j = j < 0 ? 0 : (j > 1998 ? 1998 : j);
            float4 ev = *(const float4*)(relE + (size_t)j * 64 + d0 + c4);
            Es[c4 + 0][ls] = ev.x; Es[c4 + 1][ls] = ev.y;
            Es[c4 + 2][ls] = ev.z; Es[c4 + 3][ls] = ev.w;
        }
        __syncthreads();

        const int eb = tn - tm + 60;
#pragma unroll 8
        for (int kk = 0; kk < 32; kk++) {
            float4 qv = *(const float4*)&Qs[kk][tm];
            float4 kv = *(const float4*)&Ks[kk][tn];
            float4 rv = *(const float4*)&Rs[kk][tm];
            const float* erow = &Es[kk][eb];
            float qa[4] = {qv.x, qv.y, qv.z, qv.w};
            float ka[4] = {kv.x, kv.y, kv.z, kv.w};
            float ra[4] = {rv.x, rv.y, rv.z, rv.w};
            float e[7];
#pragma unroll
            for (int t = 0; t < 7; t++) e[t] = erow[t];
#pragma unroll
            for (int i = 0; i < 4; i++)
#pragma unroll
                for (int j = 0; j < 4; j++)
                    acc[i][j] = fmaf(qa[i], ka[j],
                                     fmaf(ra[i], e[j - i + 3], acc[i][j]));
        }
    }

    float* Sb = g_S + ((size_t)bh * 1024 + q0 + tm) * 1024 + k0 + tn;
#pragma unroll
    for (int i = 0; i < 4; i++)
#pragma unroll
        for (int j = 0; j < 4; j++)
            Sb[(size_t)i * 1024 + j] = acc[i][j] * 8.0f;
}

__global__ void __launch_bounds__(256) softmax_kernel(const void* __restrict__ mask)
{
    const int row = blockIdx.x;
    const int q = row & 1023;
    const int bh = row >> 10;
    const int b = bh >> 4;
    float* Srow = g_S + (size_t)row * 1024;
    const size_t mb = ((size_t)(b << 10) + q) * 1024;
    const int tx = threadIdx.x;
    const int k = tx << 2;

    const int fl = g_mask_flags;
    const int wdt = (fl & 1) ? 2 : ((fl & 2) ? 1 : 4);

    float4 sv = *(const float4*)(Srow + k);
    float v[4] = {sv.x, sv.y, sv.z, sv.w};
    const float NEG = __int_as_float(0xff800000);

    if (wdt == 4) {
        const unsigned int* mp = (const unsigned int*)mask + mb + k;
#pragma unroll
        for (int i = 0; i < 4; i++) if (mp[i]) v[i] = NEG;
    } else if (wdt == 2) {
        const unsigned short* mp = (const unsigned short*)mask + mb + k;
#pragma unroll
        for (int i = 0; i < 4; i++) if (mp[i]) v[i] = NEG;
    } else {
        const unsigned char* mp = (const unsigned char*)mask + mb + k;
#pragma unroll
        for (int i = 0; i < 4; i++) if (mp[i]) v[i] = NEG;
    }

    float mx = fmaxf(fmaxf(v[0], v[1]), fmaxf(v[2], v[3]));
#pragma unroll
    for (int off = 16; off; off >>= 1)
        mx = fmaxf(mx, __shfl_xor_sync(0xffffffffu, mx, off));
    __shared__ float red[8];
    if ((tx & 31) == 0) red[tx >> 5] = mx;
    __syncthreads();
    float rmax = red[0];
#pragma unroll
    for (int i = 1; i < 8; i++) rmax = fmaxf(rmax, red[i]);

    float e[4], s = 0.f;
#pragma unroll
    for (int i = 0; i < 4; i++) { e[i] = expf(v[i] - rmax); s += e[i]; }
#pragma unroll
    for (int off = 16; off; off >>= 1)
        s += __shfl_xor_sync(0xffffffffu, s, off);
    __syncthreads();
    if ((tx & 31) == 0) red[tx >> 5] = s;
    __syncthreads();
    float rs = 0.f;
#pragma unroll
    for (int i = 0; i < 8; i++) rs += red[i];
    const float inv = 1.0f / rs;

    *(float4*)(Srow + k) = make_float4(e[0] * inv, e[1] * inv, e[2] * inv, e[3] * inv);
}

__global__ void __launch_bounds__(256) av_kernel()
{
    __shared__ __align__(16) float Ps[16][128];
    __shared__ __align__(16) float Vs[16][64];

    const int tx = threadIdx.x;
    const int qt = blockIdx.x;
    const int bh = blockIdx.y;
    const int b = bh >> 4, h = bh & 15;
    const int tm = (tx >> 4) << 3;
    const int tn = (tx & 15) << 2;

    const float* Pb = g_S + ((size_t)bh * 1024 + qt * 128) * 1024;
    const float* Vb = g_V + (size_t)bh * 1024 * 64;

    float acc[8][4];
#pragma unroll
    for (int i = 0; i < 8; i++)
#pragma unroll
        for (int j = 0; j < 4; j++) acc[i][j] = 0.f;

    for (int k0 = 0; k0 < 1024; k0 += 16) {
        __syncthreads();
#pragma unroll
        for (int it = 0; it < 2; it++) {
            const int idx = tx + (it << 8);
            const int qq = idx >> 2;
            const int c4 = (idx & 3) << 2;
            float4 pv = *(const float4*)(Pb + (size_t)qq * 1024 + k0 + c4);
            Ps[c4 + 0][qq] = pv.x; Ps[c4 + 1][qq] = pv.y;
            Ps[c4 + 2][qq] = pv.z; Ps[c4 + 3][qq] = pv.w;
        }
        {
            const int kk = tx >> 4;
            const int d4 = (tx & 15) << 2;
            *(float4*)&Vs[kk][d4] = *(const float4*)(Vb + (size_t)(k0 + kk) * 64 + d4);
        }
        __syncthreads();
#pragma unroll
        for (int kk = 0; kk < 16; kk++) {
            float4 a0 = *(const float4*)&Ps[kk][tm];
            float4 a1 = *(const float4*)&Ps[kk][tm + 4];
            float4 bv = *(const float4*)&Vs[kk][tn];
            float a[8]  = {a0.x, a0.y, a0.z, a0.w, a1.x, a1.y, a1.z, a1.w};
            float bb[4] = {bv.x, bv.y, bv.z, bv.w};
#pragma unroll
            for (int i = 0; i < 8; i++)
#pragma unroll
                for (int j = 0; j < 4; j++)
                    acc[i][j] = fmaf(a[i], bb[j], acc[i][j]);
        }
    }

    float* Ob = g_O + ((size_t)(b * 1024 + qt * 128 + tm)) * 1024 + h * 64 + tn;
#pragma unroll
    for (int i = 0; i < 8; i++)
#pragma unroll
        for (int j = 0; j < 4; j++)
            Ob[(size_t)i * 1024 + j] = acc[i][j];
}

// ===========================================================================
// Launch
// ===========================================================================
extern "C" void kernel_launch(void* const* d_in, const int* in_sizes, int n_in,
                              void* d_out, int out_size)
{
    const float* query = (const float*)d_in[0];
    const float* key_i = (const float*)d_in[1];
    const float* value = (const float*)d_in[2];
    const void*  mask  = d_in[3];
    const float* q_w = (const float*)d_in[4];
    const float* q_b = (const float*)d_in[5];
    const float* k_w = (const float*)d_in[6];
    const float* k_b = (const float*)d_in[7];
    const float* v_w = (const float*)d_in[8];
    const float* v_b = (const float*)d_in[9];
    const float* o_w = (const float*)d_in[10];
    const float* o_b = (const float*)d_in[11];
    const float* relE = (const float*)d_in[12];
    float* out = (float*)d_out;

    static int smem_set = 0;
    if (!smem_set) {
        cudaFuncSetAttribute(mma_gemm_kernel,
                             cudaFuncAttributeMaxDynamicSharedMemorySize,
                             SMEM_U32 * 4);
        smem_set = 1;
    }

    dim3 gg(1024 / 128, 4096 / 128);
    const size_t smem = SMEM_U32 * 4;

    mma_gemm_kernel<<<gg, 256, smem>>>(query, q_w, q_b, nullptr, 0, 0, 1);
    mma_gemm_kernel<<<gg, 256, smem>>>(key_i, k_w, k_b, nullptr, 0, 1, 1);
    mma_gemm_kernel<<<gg, 256, smem>>>(value, v_w, v_b, nullptr, 0, 2, 1);

    mask_detect_kernel<<<256, 256>>>((const unsigned int*)mask);

    logits_kernel<<<dim3(16, 16, 64), 256>>>(query, relE);
    softmax_kernel<<<65536, 256>>>(mask);
    av_kernel<<<dim3(8, 64), 256>>>();

    mma_gemm_kernel<<<gg, 256, smem>>>(nullptr, o_w, o_b, out, 1, 3, 0);
}

// round 5
// speedup vs baseline: 1.4081x; 1.0620x over previous
#include <cuda_runtime.h>
#include <cuda_bf16.h>
#include <cstdint>
#include <cstddef>

#define BB 4
#define TT 1024
#define HH 16
#define DD 64
#define CC 1024
#define MM 4096

__device__ float g_Q[(size_t)BB * HH * TT * DD];
__device__ float g_K[(size_t)BB * HH * TT * DD];
__device__ float g_V[(size_t)BB * HH * TT * DD];
__device__ float g_S[(size_t)BB * HH * TT * TT];
__device__ float g_O[(size_t)MM * CC];
__device__ int   g_mask_flags;

// ===========================================================================
// shared helpers (validated in R4)
// ===========================================================================
__device__ __forceinline__ void mma16816(float* c, const uint32_t* a,
                                         const uint32_t* b) {
    asm volatile(
        "mma.sync.aligned.m16n8k16.row.col.f32.bf16.bf16.f32 "
        "{%0,%1,%2,%3}, {%4,%5,%6,%7}, {%8,%9}, {%0,%1,%2,%3};"
        : "+f"(c[0]), "+f"(c[1]), "+f"(c[2]), "+f"(c[3])
        : "r"(a[0]), "r"(a[1]), "r"(a[2]), "r"(a[3]), "r"(b[0]), "r"(b[1]));
}

__device__ __forceinline__ void split2(float x, float y, uint32_t& hi, uint32_t& lo) {
    __nv_bfloat16 hx = __float2bfloat16(x);
    __nv_bfloat16 hy = __float2bfloat16(y);
    __nv_bfloat16 lx = __float2bfloat16(x - __bfloat162float(hx));
    __nv_bfloat16 ly = __float2bfloat16(y - __bfloat162float(hy));
    hi = ((uint32_t)__bfloat16_as_ushort(hy) << 16) | __bfloat16_as_ushort(hx);
    lo = ((uint32_t)__bfloat16_as_ushort(ly) << 16) | __bfloat16_as_ushort(lx);
}

// A-operand u32 slot: 128-row tile, k arbitrary (regions stacked by k>>4)
__device__ __forceinline__ int a_slot(int row, int k) {
    const int kstep = k >> 4, kk = k & 15;
    const int mt = row >> 4, rit = row & 15;
    const int lane = ((rit & 7) << 2) | ((kk >> 1) & 3);
    const int r = (rit >> 3) | (((kk >> 3) & 1) << 1);
    return (((kstep << 3) + mt) << 7) + (lane << 2) + r;
}
// B-operand u32 slot with NT n-tiles
__device__ __forceinline__ int b_slotN(int n, int k, int NT) {
    const int kstep = k >> 4, kk = k & 15;
    const int nt = n >> 3, gc = n & 7;
    const int lane = (gc << 2) | ((kk >> 1) & 3);
    const int r = (kk >> 3) & 1;
    return (((kstep * NT) + nt) << 6) + (lane << 1) + r;
}

// ===========================================================================
// mask dtype-width detector (validated)
// ===========================================================================
__global__ void mask_detect_kernel(const unsigned int* __restrict__ m) {
    unsigned f = 0;
    for (unsigned i = blockIdx.x * blockDim.x + threadIdx.x; i < (1u << 20);
         i += blockDim.x * gridDim.x) {
        unsigned w = m[i];
        if (w == 0u) continue;
        unsigned lo = w & 0xFFFFu;
        if (lo == 0x3F80u || lo == 0x3C00u) f |= 1u;
        if (((w & 0xFEFEFEFEu) == 0u) && w > 1u) f |= 2u;
    }
    if (f) atomicOr(&g_mask_flags, (int)f);
}

// ===========================================================================
// HMMA bf16x3 projection GEMM (validated R4, unchanged)
// ===========================================================================
#define CHUNK_U32 2048
#define BUF_U32   (4 * CHUNK_U32)
#define SMEM_U32  (2 * BUF_U32)

__global__ void __launch_bounds__(256, 1) mma_gemm_kernel(
    const float* __restrict__ extA, const float* __restrict__ W,
    const float* __restrict__ bias, float* extDst, int srcsel, int dstsel,
    int headmode)
{
    extern __shared__ __align__(16) uint32_t smem[];
    const int tid = threadIdx.x;
    const int wid = tid >> 5;
    const int lane = tid & 31;
    const int wm = wid >> 2;
    const int wn = wid & 3;
    const int g = lane >> 2;
    const int tig = lane & 3;

    const float* A = srcsel ? g_O : extA;
    float* Cout = (dstsel == 0) ? g_Q : (dstsel == 1) ? g_K :
                  (dstsel == 2) ? g_V : extDst;
    const int bm = blockIdx.y << 7;
    const int bn = blockIdx.x << 7;

    const int lrow = tid >> 1;
    const int lk0 = (tid & 1) << 4;
    const float* Agp = A + (size_t)(bm + lrow) * 1024 + lk0;
    const float* Bgp = W + (size_t)(bn + lrow) * 1024 + lk0;

    float acc[4][4][4];
#pragma unroll
    for (int i = 0; i < 4; i++)
#pragma unroll
        for (int j = 0; j < 4; j++)
#pragma unroll
            for (int r = 0; r < 4; r++) acc[i][j][r] = 0.f;

    float4 pa[4], pb[4];
#pragma unroll
    for (int q = 0; q < 4; q++) {
        pa[q] = *(const float4*)(Agp + (q << 2));
        pb[q] = *(const float4*)(Bgp + (q << 2));
    }

    auto stage = [&](int buf) {
        uint32_t* Ah = smem + buf * BUF_U32;
        uint32_t* Al = Ah + CHUNK_U32;
        uint32_t* Bh = Al + CHUNK_U32;
        uint32_t* Bl = Bh + CHUNK_U32;
#pragma unroll
        for (int q = 0; q < 4; q++) {
            const int kq = lk0 + (q << 2);
            uint32_t h0, l0, h1, l1;
            split2(pa[q].x, pa[q].y, h0, l0);
            split2(pa[q].z, pa[q].w, h1, l1);
            int s0 = a_slot(lrow, kq) & 0xFFF, s1 = a_slot(lrow, kq + 2) & 0xFFF;
            // (k<32 here so a_slot fits 2 kstep regions; mask keeps region math)
            s0 = a_slot(lrow, kq); s1 = a_slot(lrow, kq + 2);
            Ah[s0] = h0; Al[s0] = l0; Ah[s1] = h1; Al[s1] = l1;
            split2(pb[q].x, pb[q].y, h0, l0);
            split2(pb[q].z, pb[q].w, h1, l1);
            s0 = b_slotN(lrow, kq, 16); s1 = b_slotN(lrow, kq + 2, 16);
            Bh[s0] = h0; Bl[s0] = l0; Bh[s1] = h1; Bl[s1] = l1;
        }
    };

    stage(0);
    __syncthreads();

#pragma unroll 1
    for (int s = 0; s < 32; s++) {
        if (s < 31) {
            const int koff = (s + 1) << 5;
#pragma unroll
            for (int q = 0; q < 4; q++) {
                pa[q] = *(const float4*)(Agp + koff + (q << 2));
                pb[q] = *(const float4*)(Bgp + koff + (q << 2));
            }
        }
        const uint32_t* Ah = smem + (s & 1) * BUF_U32;
        const uint32_t* Al = Ah + CHUNK_U32;
        const uint32_t* Bh = Al + CHUNK_U32;
        const uint32_t* Bl = Bh + CHUNK_U32;

#pragma unroll
        for (int ks = 0; ks < 2; ks++) {
            uint32_t bh[4][2], bl[4][2];
#pragma unroll
            for (int j = 0; j < 4; j++) {
                const int nt = (wn << 2) + j;
                const int bi = (((ks << 4) + nt) << 6) + (lane << 1);
                *(uint2*)bh[j] = *(const uint2*)(Bh + bi);
                *(uint2*)bl[j] = *(const uint2*)(Bl + bi);
            }
#pragma unroll
            for (int i = 0; i < 4; i++) {
                const int mt = (wm << 2) + i;
                const int ai = (((ks << 3) + mt) << 7) + (lane << 2);
                uint32_t ah[4], al[4];
                *(uint4*)ah = *(const uint4*)(Ah + ai);
                *(uint4*)al = *(const uint4*)(Al + ai);
#pragma unroll
                for (int j = 0; j < 4; j++) {
                    mma16816(acc[i][j], ah, bh[j]);
                    mma16816(acc[i][j], ah, bl[j]);
                    mma16816(acc[i][j], al, bh[j]);
                }
            }
        }
        __syncthreads();
        if (s < 31) stage((s + 1) & 1);
        __syncthreads();
    }

#pragma unroll
    for (int i = 0; i < 4; i++) {
        const int m0 = bm + (wm << 6) + (i << 4) + g;
#pragma unroll
        for (int j = 0; j < 4; j++) {
            const int n = bn + (wn << 5) + (j << 3) + (tig << 1);
            const float2 bv = *(const float2*)(bias + n);
#pragma unroll
            for (int half = 0; half < 2; half++) {
                const int m = m0 + (half << 3);
                float2 o;
                o.x = acc[i][j][half * 2 + 0] + bv.x;
                o.y = acc[i][j][half * 2 + 1] + bv.y;
                size_t idx;
                if (headmode) {
                    idx = (((size_t)((m >> 10) * 16 + (n >> 6)) * 1024 +
                            (size_t)(m & 1023)) << 6) + (n & 63);
                } else {
                    idx = (size_t)m * 1024 + n;
                }
                *(float2*)(Cout + idx) = o;
            }
        }
    }
}

// ===========================================================================
// qk_mma: S[bh][q][k] = Q.K (UNSCALED), 128x128 tile, bf16x3 mma
// 8 warps, warp wid owns q rows wid*16..+15 x all 128 k.
// ===========================================================================
#define QK_SMEM_BYTES 67584     // max(64KB frag tiles, 128*132*4 stage)

__global__ void __launch_bounds__(256, 1) qk_mma_kernel()
{
    extern __shared__ __align__(16) uint32_t sm[];
    const int tid = threadIdx.x;
    const int wid = tid >> 5;
    const int lane = tid & 31;
    const int g = lane >> 2;
    const int tig = lane & 3;
    const int kt = blockIdx.x, qt = blockIdx.y, bh = blockIdx.z;
    const int q0 = qt << 7, k0 = kt << 7;

    uint32_t* Qh = sm;
    uint32_t* Ql = sm + 4096;
    uint32_t* Kh = sm + 8192;
    uint32_t* Kl = sm + 12288;

    {   // stage Q tile (A-order) and K tile (B-order, NT=16)
        const int row = tid >> 1;
        const int d0 = (tid & 1) << 5;
        const float* qs = g_Q + ((size_t)bh * 1024 + q0 + row) * 64 + d0;
        const float* ks = g_K + ((size_t)bh * 1024 + k0 + row) * 64 + d0;
#pragma unroll
        for (int qi = 0; qi < 8; qi++) {
            const int kq = d0 + (qi << 2);
            float4 v = *(const float4*)(qs + (qi << 2));
            uint32_t h0, l0, h1, l1;
            split2(v.x, v.y, h0, l0);
            split2(v.z, v.w, h1, l1);
            int s0 = a_slot(row, kq), s1 = a_slot(row, kq + 2);
            Qh[s0] = h0; Ql[s0] = l0; Qh[s1] = h1; Ql[s1] = l1;
            v = *(const float4*)(ks + (qi << 2));
            split2(v.x, v.y, h0, l0);
            split2(v.z, v.w, h1, l1);
            s0 = b_slotN(row, kq, 16); s1 = b_slotN(row, kq + 2, 16);
            Kh[s0] = h0; Kl[s0] = l0; Kh[s1] = h1; Kl[s1] = l1;
        }
    }
    __syncthreads();

    float acc[16][4];
#pragma unroll
    for (int j = 0; j < 16; j++)
#pragma unroll
        for (int r = 0; r < 4; r++) acc[j][r] = 0.f;

    uint32_t ah[4][4], al[4][4];
#pragma unroll
    for (int s = 0; s < 4; s++) {
        const int ai = (((s << 3) + wid) << 7) + (lane << 2);
        *(uint4*)ah[s] = *(const uint4*)(Qh + ai);
        *(uint4*)al[s] = *(const uint4*)(Ql + ai);
    }
#pragma unroll
    for (int j = 0; j < 16; j++) {
#pragma unroll
        for (int s = 0; s < 4; s++) {
            uint32_t bh2[2], bl2[2];
            const int bi = (((s << 4) + j) << 6) + (lane << 1);
            *(uint2*)bh2 = *(const uint2*)(Kh + bi);
            *(uint2*)bl2 = *(const uint2*)(Kl + bi);
            mma16816(acc[j], ah[s], bh2);
            mma16816(acc[j], ah[s], bl2);
            mma16816(acc[j], al[s], bh2);
        }
    }
    __syncthreads();

    // restage through padded smem for coalesced S writes
    float* stg = (float*)sm;
    {
        const int r0 = (wid << 4) + g;
#pragma unroll
        for (int j = 0; j < 16; j++) {
            const int col = (j << 3) + (tig << 1);
            *(float2*)&stg[r0 * 132 + col] = make_float2(acc[j][0], acc[j][1]);
            *(float2*)&stg[(r0 + 8) * 132 + col] = make_float2(acc[j][2], acc[j][3]);
        }
    }
    __syncthreads();

    float* Sb = g_S + ((size_t)bh << 20) + (size_t)q0 * 1024 + k0;
#pragma unroll
    for (int i = 0; i < 16; i++) {
        const int fi = tid + (i << 8);
        const int row = fi >> 5;
        const int c4 = (fi & 31) << 2;
        *(float4*)(Sb + (size_t)row * 1024 + c4) = *(const float4*)&stg[row * 132 + c4];
    }
}

// ===========================================================================
// rpe: S = (S + rawq . rel_emb[clip(k-q+999)]) * 8  (read-modify-write)
// derived from validated logits kernel, QK half removed.
// ===========================================================================
__global__ void __launch_bounds__(256) rpe_kernel(
    const float* __restrict__ rawq, const float* __restrict__ relE)
{
    __shared__ __align__(16) float Rs[32][64];
    __shared__ __align__(16) float Es[32][128];

    const int tx = threadIdx.x;
    const int kt = blockIdx.x, qt = blockIdx.y, bh = blockIdx.z;
    const int b = bh >> 4, h = bh & 15;
    const int q0 = qt << 6, k0 = kt << 6;
    const int base = k0 - q0 + 999;
    const int tm = (tx >> 4) << 2;
    const int tn = (tx & 15) << 2;

    const float* Rb = rawq + ((size_t)(b * 1024 + q0)) * 1024 + h * 64;

    float acc[4][4];
#pragma unroll
    for (int i = 0; i < 4; i++)
#pragma unroll
        for (int j = 0; j < 4; j++) acc[i][j] = 0.f;

    for (int d0 = 0; d0 < 64; d0 += 32) {
        __syncthreads();
        {
            const int it = tx;
            for (int idx = it; idx < 512; idx += 256) {
                const int qq = idx >> 3;
                const int c4 = (idx & 7) << 2;
                float4 rv = *(const float4*)(Rb + (size_t)qq * 1024 + d0 + c4);
                Rs[c4 + 0][qq] = rv.x; Rs[c4 + 1][qq] = rv.y;
                Rs[c4 + 2][qq] = rv.z; Rs[c4 + 3][qq] = rv.w;
            }
        }
        for (int idx = tx; idx < 127 * 8; idx += 256) {
            const int ls = idx >> 3;
            const int c4 = (idx & 7) << 2;
            int j = base + ls - 63;
            j = j < 0 ? 0 : (j > 1998 ? 1998 : j);
            float4 ev = *(const float4*)(relE + (size_t)j * 64 + d0 + c4);
            Es[c4 + 0][ls] = ev.x; Es[c4 + 1][ls] = ev.y;
            Es[c4 + 2][ls] = ev.z; Es[c4 + 3][ls] = ev.w;
        }
        __syncthreads();

        const int eb = tn - tm + 60;
#pragma unroll 8
        for (int kk = 0; kk < 32; kk++) {
            float4 rv = *(const float4*)&Rs[kk][tm];
            const float* erow = &Es[kk][eb];
            float ra[4] = {rv.x, rv.y, rv.z, rv.w};
            float e[7];
#pragma unroll
            for (int t = 0; t < 7; t++) e[t] = erow[t];
#pragma unroll
            for (int i = 0; i < 4; i++)
#pragma unroll
                for (int j = 0; j < 4; j++)
                    acc[i][j] = fmaf(ra[i], e[j - i + 3], acc[i][j]);
        }
    }

    float* Sb = g_S + ((size_t)bh * 1024 + q0 + tm) * 1024 + k0 + tn;
#pragma unroll
    for (int i = 0; i < 4; i++) {
        float4 sv = *(const float4*)(Sb + (size_t)i * 1024);
        sv.x = (sv.x + acc[i][0]) * 8.0f;
        sv.y = (sv.y + acc[i][1]) * 8.0f;
        sv.z = (sv.z + acc[i][2]) * 8.0f;
        sv.w = (sv.w + acc[i][3]) * 8.0f;
        *(float4*)(Sb + (size_t)i * 1024) = sv;
    }
}

// ===========================================================================
// softmax (validated, unchanged)
// ===========================================================================
__global__ void __launch_bounds__(256) softmax_kernel(const void* __restrict__ mask)
{
    const int row = blockIdx.x;
    const int q = row & 1023;
    const int bh = row >> 10;
    const int b = bh >> 4;
    float* Srow = g_S + (size_t)row * 1024;
    const size_t mb = ((size_t)(b << 10) + q) * 1024;
    const int tx = threadIdx.x;
    const int k = tx << 2;

    const int fl = g_mask_flags;
    const int wdt = (fl & 1) ? 2 : ((fl & 2) ? 1 : 4);

    float4 sv = *(const float4*)(Srow + k);
    float v[4] = {sv.x, sv.y, sv.z, sv.w};
    const float NEG = __int_as_float(0xff800000);

    if (wdt == 4) {
        const unsigned int* mp = (const unsigned int*)mask + mb + k;
#pragma unroll
        for (int i = 0; i < 4; i++) if (mp[i]) v[i] = NEG;
    } else if (wdt == 2) {
        const unsigned short* mp = (const unsigned short*)mask + mb + k;
#pragma unroll
        for (int i = 0; i < 4; i++) if (mp[i]) v[i] = NEG;
    } else {
        const unsigned char* mp = (const unsigned char*)mask + mb + k;
#pragma unroll
        for (int i = 0; i < 4; i++) if (mp[i]) v[i] = NEG;
    }

    float mx = fmaxf(fmaxf(v[0], v[1]), fmaxf(v[2], v[3]));
#pragma unroll
    for (int off = 16; off; off >>= 1)
        mx = fmaxf(mx, __shfl_xor_sync(0xffffffffu, mx, off));
    __shared__ float red[8];
    if ((tx & 31) == 0) red[tx >> 5] = mx;
    __syncthreads();
    float rmax = red[0];
#pragma unroll
    for (int i = 1; i < 8; i++) rmax = fmaxf(rmax, red[i]);

    float e[4], s = 0.f;
#pragma unroll
    for (int i = 0; i < 4; i++) { e[i] = expf(v[i] - rmax); s += e[i]; }
#pragma unroll
    for (int off = 16; off; off >>= 1)
        s += __shfl_xor_sync(0xffffffffu, s, off);
    __syncthreads();
    if ((tx & 31) == 0) red[tx >> 5] = s;
    __syncthreads();
    float rs = 0.f;
#pragma unroll
    for (int i = 0; i < 8; i++) rs += red[i];
    const float inv = 1.0f / rs;

    *(float4*)(Srow + k) = make_float4(e[0] * inv, e[1] * inv, e[2] * inv, e[3] * inv);
}

// ===========================================================================
// av_mma: O = P*V per bh, 128-q tile, 8 key-chunks of 128, bf16 split 3-term
// ===========================================================================
#define AV_SMEM_BYTES 98304

__global__ void __launch_bounds__(256, 1) av_mma_kernel()
{
    extern __shared__ __align__(16) uint32_t sm[];
    uint32_t* Ph = sm;
    uint32_t* Pl = sm + 8192;
    uint32_t* Vh = sm + 16384;
    uint32_t* Vl = sm + 20480;

    const int tid = threadIdx.x;
    const int wid = tid >> 5;
    const int lane = tid & 31;
    const int g = lane >> 2;
    const int tig = lane & 3;
    const int qt = blockIdx.x;
    const int bh = blockIdx.y;
    const int b = bh >> 4, h = bh & 15;
    const int q0 = qt << 7;

    float acc[8][4];
#pragma unroll
    for (int j = 0; j < 8; j++)
#pragma unroll
        for (int r = 0; r < 4; r++) acc[j][r] = 0.f;

    const int kp = tid >> 2;               // key-pair 0..63
    const int dq = (tid & 3) << 4;         // d base 0/16/32/48

#pragma unroll 1
    for (int kc = 0; kc < 8; kc++) {
        // ---- LDG phase ----
        float4 pv[16];
#pragma unroll
        for (int i = 0; i < 16; i++) {
            const int fi = tid + (i << 8);
            const int prow = fi >> 5;
            const int pc4 = (fi & 31) << 2;
            pv[i] = *(const float4*)(g_S + ((size_t)bh * 1024 + q0 + prow) * 1024 +
                                     (kc << 7) + pc4);
        }
        float4 vv[8];
        {
            const size_t vb = (size_t)bh * 65536 + (size_t)((kc << 7) + (kp << 1)) * 64 + dq;
#pragma unroll
            for (int m = 0; m < 4; m++) {
                vv[m] = *(const float4*)(g_V + vb + (m << 2));
                vv[4 + m] = *(const float4*)(g_V + vb + 64 + (m << 2));
            }
        }
        __syncthreads();   // prior mma reads done before overwrite

        // ---- stage ----
#pragma unroll
        for (int i = 0; i < 16; i++) {
            const int fi = tid + (i << 8);
            const int prow = fi >> 5;
            const int pc4 = (fi & 31) << 2;
            uint32_t h0, l0, h1, l1;
            split2(pv[i].x, pv[i].y, h0, l0);
            split2(pv[i].z, pv[i].w, h1, l1);
            const int s0 = a_slot(prow, pc4), s1 = a_slot(prow, pc4 + 2);
            Ph[s0] = h0; Pl[s0] = l0; Ph[s1] = h1; Pl[s1] = l1;
        }
#pragma unroll
        for (int m = 0; m < 4; m++) {
            const float* v0 = (const float*)&vv[m];
            const float* v1 = (const float*)&vv[4 + m];
#pragma unroll
            for (int dd = 0; dd < 4; dd++) {
                uint32_t hi, lo;
                split2(v0[dd], v1[dd], hi, lo);
                const int slot = b_slotN(dq + (m << 2) + dd, kp << 1, 8);
                Vh[slot] = hi; Vl[slot] = lo;
            }
        }
        __syncthreads();

        // ---- mma ----
#pragma unroll
        for (int s = 0; s < 8; s++) {
            uint32_t ah[4], al[4];
            const int ai = (((s << 3) + wid) << 7) + (lane << 2);
            *(uint4*)ah = *(const uint4*)(Ph + ai);
            *(uint4*)al = *(const uint4*)(Pl + ai);
#pragma unroll
            for (int j = 0; j < 8; j++) {
                uint32_t bh2[2], bl2[2];
                const int bi = (((s << 3) + j) << 6) + (lane << 1);
                *(uint2*)bh2 = *(const uint2*)(Vh + bi);
                *(uint2*)bl2 = *(const uint2*)(Vl + bi);
                mma16816(acc[j], ah, bh2);
                mma16816(acc[j], ah, bl2);
                mma16816(acc[j], al, bh2);
            }
        }
    }

    // epilogue: O[b*1024+q][h*64+d]
    const int qrow = q0 + (wid << 4) + g;
#pragma unroll
    for (int j = 0; j < 8; j++) {
        const int d = (j << 3) + (tig << 1);
        float* op = g_O + ((size_t)(b * 1024 + qrow)) * 1024 + h * 64 + d;
        *(float2*)op = make_float2(acc[j][0], acc[j][1]);
        *(float2*)(op + (size_t)8 * 1024) = make_float2(acc[j][2], acc[j][3]);
    }
}

// ===========================================================================
// Launch
// ===========================================================================
extern "C" void kernel_launch(void* const* d_in, const int* in_sizes, int n_in,
                              void* d_out, int out_size)
{
    const float* query = (const float*)d_in[0];
    const float* key_i = (const float*)d_in[1];
    const float* value = (const float*)d_in[2];
    const void*  mask  = d_in[3];
    const float* q_w = (const float*)d_in[4];
    const float* q_b = (const float*)d_in[5];
    const float* k_w = (const float*)d_in[6];
    const float* k_b = (const float*)d_in[7];
    const float* v_w = (const float*)d_in[8];
    const float* v_b = (const float*)d_in[9];
    const float* o_w = (const float*)d_in[10];
    const float* o_b = (const float*)d_in[11];
    const float* relE = (const float*)d_in[12];
    float* out = (float*)d_out;

    static int attr_set = 0;
    if (!attr_set) {
        cudaFuncSetAttribute(mma_gemm_kernel,
                             cudaFuncAttributeMaxDynamicSharedMemorySize,
                             SMEM_U32 * 4);
        cudaFuncSetAttribute(qk_mma_kernel,
                             cudaFuncAttributeMaxDynamicSharedMemorySize,
                             QK_SMEM_BYTES);
        cudaFuncSetAttribute(av_mma_kernel,
                             cudaFuncAttributeMaxDynamicSharedMemorySize,
                             AV_SMEM_BYTES);
        attr_set = 1;
    }

    dim3 gg(1024 / 128, 4096 / 128);
    const size_t gsmem = SMEM_U32 * 4;

    mma_gemm_kernel<<<gg, 256, gsmem>>>(query, q_w, q_b, nullptr, 0, 0, 1);
    mma_gemm_kernel<<<gg, 256, gsmem>>>(key_i, k_w, k_b, nullptr, 0, 1, 1);
    mma_gemm_kernel<<<gg, 256, gsmem>>>(value, v_w, v_b, nullptr, 0, 2, 1);

    mask_detect_kernel<<<256, 256>>>((const unsigned int*)mask);

    qk_mma_kernel<<<dim3(8, 8, 64), 256, QK_SMEM_BYTES>>>();
    rpe_kernel<<<dim3(16, 16, 64), 256>>>(query, relE);
    softmax_kernel<<<65536, 256>>>(mask);
    av_mma_kernel<<<dim3(8, 64), 256, AV_SMEM_BYTES>>>();

    mma_gemm_kernel<<<gg, 256, gsmem>>>(nullptr, o_w, o_b, out, 1, 3, 0);
}

// round 6
// speedup vs baseline: 1.7201x; 1.2216x over previous
#include <cuda_runtime.h>
#include <cuda_bf16.h>
#include <cstdint>
#include <cstddef>

#define BB 4
#define TT 1024
#define HH 16
#define DD 64
#define CC 1024
#define MM 4096

__device__ float g_Q[(size_t)BB * HH * TT * DD];
__device__ float g_K[(size_t)BB * HH * TT * DD];
__device__ float g_V[(size_t)BB * HH * TT * DD];
__device__ float g_S[(size_t)BB * HH * TT * TT];
__device__ float g_O[(size_t)MM * CC];
__device__ int   g_mask_flags;

// fragment-ordered bf16 planes (u32 = packed bf16x2)
__device__ uint32_t g_Ah[(size_t)MM * CC / 2];   // 8 MB
__device__ uint32_t g_Al[(size_t)MM * CC / 2];   // 8 MB
__device__ uint32_t g_Wh[(size_t)CC * CC / 2];   // 2 MB
__device__ uint32_t g_Wl[(size_t)CC * CC / 2];   // 2 MB

// ===========================================================================
// shared helpers (validated R4/R5)
// ===========================================================================
__device__ __forceinline__ void mma16816(float* c, const uint32_t* a,
                                         const uint32_t* b) {
    asm volatile(
        "mma.sync.aligned.m16n8k16.row.col.f32.bf16.bf16.f32 "
        "{%0,%1,%2,%3}, {%4,%5,%6,%7}, {%8,%9}, {%0,%1,%2,%3};"
        : "+f"(c[0]), "+f"(c[1]), "+f"(c[2]), "+f"(c[3])
        : "r"(a[0]), "r"(a[1]), "r"(a[2]), "r"(a[3]), "r"(b[0]), "r"(b[1]));
}

__device__ __forceinline__ void split2(float x, float y, uint32_t& hi, uint32_t& lo) {
    __nv_bfloat16 hx = __float2bfloat16(x);
    __nv_bfloat16 hy = __float2bfloat16(y);
    __nv_bfloat16 lx = __float2bfloat16(x - __bfloat162float(hx));
    __nv_bfloat16 ly = __float2bfloat16(y - __bfloat162float(hy));
    hi = ((uint32_t)__bfloat16_as_ushort(hy) << 16) | __bfloat16_as_ushort(hx);
    lo = ((uint32_t)__bfloat16_as_ushort(ly) << 16) | __bfloat16_as_ushort(lx);
}

__device__ __forceinline__ int a_slot(int row, int k) {
    const int kstep = k >> 4, kk = k & 15;
    const int mt = row >> 4, rit = row & 15;
    const int lane = ((rit & 7) << 2) | ((kk >> 1) & 3);
    const int r = (rit >> 3) | (((kk >> 3) & 1) << 1);
    return (((kstep << 3) + mt) << 7) + (lane << 2) + r;
}
__device__ __forceinline__ int b_slotN(int n, int k, int NT) {
    const int kstep = k >> 4, kk = k & 15;
    const int nt = n >> 3, gc = n & 7;
    const int lane = (gc << 2) | ((kk >> 1) & 3);
    const int r = (kk >> 3) & 1;
    return (((kstep * NT) + nt) << 6) + (lane << 1) + r;
}

// ===========================================================================
// one-shot converters: fp32 row-major -> fragment-ordered bf16 hi/lo planes
// A-plane region (rb, ks): 1024 u32 = mt(8) x lane(32) x r(4)
// ===========================================================================
__global__ void __launch_bounds__(256) conv_a_kernel(const float* __restrict__ ext,
                                                     int srcsel)
{
    const float* src = srcsel ? g_O : ext;
    const uint32_t o = blockIdx.x * 256 + threadIdx.x;      // 0 .. 2M-1
    const uint32_t region = o >> 10;
    const uint32_t rb = region >> 6, ks = region & 63;
    const uint32_t ol = o & 1023;
    const uint32_t mt = ol >> 7;
    const uint32_t lane = (ol >> 2) & 31;
    const uint32_t r = ol & 3;
    const uint32_t rit = ((r & 1) << 3) | (lane >> 2);
    const uint32_t kk = ((r >> 1) << 3) | ((lane & 3) << 1);
    const uint32_t row = (rb << 7) + (mt << 4) + rit;
    const uint32_t k = (ks << 4) + kk;
    const float2 v = *(const float2*)(src + (size_t)row * 1024 + k);
    uint32_t hi, lo;
    split2(v.x, v.y, hi, lo);
    g_Ah[o] = hi;
    g_Al[o] = lo;
}

// B-plane region (nb, ks): 1024 u32 = nt(16) x lane(32) x r(2)
__global__ void __launch_bounds__(256) conv_b_kernel(const float* __restrict__ w)
{
    const uint32_t o = blockIdx.x * 256 + threadIdx.x;      // 0 .. 512K-1
    const uint32_t region = o >> 10;
    const uint32_t nb = region >> 6, ks = region & 63;
    const uint32_t ol = o & 1023;
    const uint32_t nt = ol >> 6;
    const uint32_t lane = (ol >> 1) & 31;
    const uint32_t r = ol & 1;
    const uint32_t gc = lane >> 2;
    const uint32_t kk = (r << 3) | ((lane & 3) << 1);
    const uint32_t n = (nb << 7) + (nt << 3) + gc;
    const uint32_t k = (ks << 4) + kk;
    const float2 v = *(const float2*)(w + (size_t)n * 1024 + k);
    uint32_t hi, lo;
    split2(v.x, v.y, hi, lo);
    g_Wh[o] = hi;
    g_Wl[o] = lo;
}

// ===========================================================================
// fragment-direct projection GEMM: no smem, no converts in loop.
// grid (8 nb, 32 rb), 8 warps: wm=wid>>2 (0..1), wn=wid&3 (0..3)
// ===========================================================================
__global__ void __launch_bounds__(256, 2) gemm_frag_kernel(
    const float* __restrict__ bias, float* extDst, int dstsel, int headmode)
{
    const int tid = threadIdx.x;
    const int wid = tid >> 5;
    const int lane = tid & 31;
    const int wm = wid >> 2;
    const int wn = wid & 3;
    const int g = lane >> 2;
    const int tig = lane & 3;
    const int nb = blockIdx.x;
    const int rb = blockIdx.y;

    float* Cout = (dstsel == 0) ? g_Q : (dstsel == 1) ? g_K :
                  (dstsel == 2) ? g_V : extDst;

    float acc[4][4][4];
#pragma unroll
    for (int i = 0; i < 4; i++)
#pragma unroll
        for (int j = 0; j < 4; j++)
#pragma unroll
            for (int r = 0; r < 4; r++) acc[i][j][r] = 0.f;

#pragma unroll 1
    for (int ks = 0; ks < 64; ks++) {
        const size_t abase = (size_t)((((rb << 6) + ks) << 3) + (wm << 2)) * 128 +
                             (lane << 2);
        const size_t bbase = (size_t)((((nb << 6) + ks) << 4) + (wn << 2)) * 64 +
                             (lane << 1);
        uint4 ah[4], al[4];
        uint2 bh[4], bl[4];
#pragma unroll
        for (int i = 0; i < 4; i++) {
            ah[i] = *(const uint4*)(g_Ah + abase + (i << 7));
            al[i] = *(const uint4*)(g_Al + abase + (i << 7));
        }
#pragma unroll
        for (int j = 0; j < 4; j++) {
            bh[j] = *(const uint2*)(g_Wh + bbase + (j << 6));
            bl[j] = *(const uint2*)(g_Wl + bbase + (j << 6));
        }
#pragma unroll
        for (int i = 0; i < 4; i++)
#pragma unroll
            for (int j = 0; j < 4; j++) {
                mma16816(acc[i][j], (const uint32_t*)&ah[i], (const uint32_t*)&bh[j]);
                mma16816(acc[i][j], (const uint32_t*)&ah[i], (const uint32_t*)&bl[j]);
                mma16816(acc[i][j], (const uint32_t*)&al[i], (const uint32_t*)&bh[j]);
            }
    }

    const int bm = rb << 7;
    const int bn = nb << 7;
#pragma unroll
    for (int i = 0; i < 4; i++) {
        const int m0 = bm + (wm << 6) + (i << 4) + g;
#pragma unroll
        for (int j = 0; j < 4; j++) {
            const int n = bn + (wn << 5) + (j << 3) + (tig << 1);
            const float2 bv = *(const float2*)(bias + n);
#pragma unroll
            for (int half = 0; half < 2; half++) {
                const int m = m0 + (half << 3);
                float2 o;
                o.x = acc[i][j][half * 2 + 0] + bv.x;
                o.y = acc[i][j][half * 2 + 1] + bv.y;
                size_t idx;
                if (headmode) {
                    idx = (((size_t)((m >> 10) * 16 + (n >> 6)) * 1024 +
                            (size_t)(m & 1023)) << 6) + (n & 63);
                } else {
                    idx = (size_t)m * 1024 + n;
                }
                *(float2*)(Cout + idx) = o;
            }
        }
    }
}

// ===========================================================================
// mask dtype-width detector (validated)
// ===========================================================================
__global__ void mask_detect_kernel(const unsigned int* __restrict__ m) {
    unsigned f = 0;
    for (unsigned i = blockIdx.x * blockDim.x + threadIdx.x; i < (1u << 20);
         i += blockDim.x * gridDim.x) {
        unsigned w = m[i];
        if (w == 0u) continue;
        unsigned lo = w & 0xFFFFu;
        if (lo == 0x3F80u || lo == 0x3C00u) f |= 1u;
        if (((w & 0xFEFEFEFEu) == 0u) && w > 1u) f |= 2u;
    }
    if (f) atomicOr(&g_mask_flags, (int)f);
}

// ===========================================================================
// qk_mma (validated R5, unchanged)
// ===========================================================================
#define QK_SMEM_BYTES 67584

__global__ void __launch_bounds__(256, 1) qk_mma_kernel()
{
    extern __shared__ __align__(16) uint32_t sm[];
    const int tid = threadIdx.x;
    const int wid = tid >> 5;
    const int lane = tid & 31;
    const int g = lane >> 2;
    const int tig = lane & 3;
    const int kt = blockIdx.x, qt = blockIdx.y, bh = blockIdx.z;
    const int q0 = qt << 7, k0 = kt << 7;

    uint32_t* Qh = sm;
    uint32_t* Ql = sm + 4096;
    uint32_t* Kh = sm + 8192;
    uint32_t* Kl = sm + 12288;

    {
        const int row = tid >> 1;
        const int d0 = (tid & 1) << 5;
        const float* qs = g_Q + ((size_t)bh * 1024 + q0 + row) * 64 + d0;
        const float* ks = g_K + ((size_t)bh * 1024 + k0 + row) * 64 + d0;
#pragma unroll
        for (int qi = 0; qi < 8; qi++) {
            const int kq = d0 + (qi << 2);
            float4 v = *(const float4*)(qs + (qi << 2));
            uint32_t h0, l0, h1, l1;
            split2(v.x, v.y, h0, l0);
            split2(v.z, v.w, h1, l1);
            int s0 = a_slot(row, kq), s1 = a_slot(row, kq + 2);
            Qh[s0] = h0; Ql[s0] = l0; Qh[s1] = h1; Ql[s1] = l1;
            v = *(const float4*)(ks + (qi << 2));
            split2(v.x, v.y, h0, l0);
            split2(v.z, v.w, h1, l1);
            s0 = b_slotN(row, kq, 16); s1 = b_slotN(row, kq + 2, 16);
            Kh[s0] = h0; Kl[s0] = l0; Kh[s1] = h1; Kl[s1] = l1;
        }
    }
    __syncthreads();

    float acc[16][4];
#pragma unroll
    for (int j = 0; j < 16; j++)
#pragma unroll
        for (int r = 0; r < 4; r++) acc[j][r] = 0.f;

    uint32_t ah[4][4], al[4][4];
#pragma unroll
    for (int s = 0; s < 4; s++) {
        const int ai = (((s << 3) + wid) << 7) + (lane << 2);
        *(uint4*)ah[s] = *(const uint4*)(Qh + ai);
        *(uint4*)al[s] = *(const uint4*)(Ql + ai);
    }
#pragma unroll
    for (int j = 0; j < 16; j++) {
#pragma unroll
        for (int s = 0; s < 4; s++) {
            uint32_t bh2[2], bl2[2];
            const int bi = (((s << 4) + j) << 6) + (lane << 1);
            *(uint2*)bh2 = *(const uint2*)(Kh + bi);
            *(uint2*)bl2 = *(const uint2*)(Kl + bi);
            mma16816(acc[j], ah[s], bh2);
            mma16816(acc[j], ah[s], bl2);
            mma16816(acc[j], al[s], bh2);
        }
    }
    __syncthreads();

    float* stg = (float*)sm;
    {
        const int r0 = (wid << 4) + g;
#pragma unroll
        for (int j = 0; j < 16; j++) {
            const int col = (j << 3) + (tig << 1);
            *(float2*)&stg[r0 * 132 + col] = make_float2(acc[j][0], acc[j][1]);
            *(float2*)&stg[(r0 + 8) * 132 + col] = make_float2(acc[j][2], acc[j][3]);
        }
    }
    __syncthreads();

    float* Sb = g_S + ((size_t)bh << 20) + (size_t)q0 * 1024 + k0;
#pragma unroll
    for (int i = 0; i < 16; i++) {
        const int fi = tid + (i << 8);
        const int row = fi >> 5;
        const int c4 = (fi & 31) << 2;
        *(float4*)(Sb + (size_t)row * 1024 + c4) = *(const float4*)&stg[row * 132 + c4];
    }
}

// ===========================================================================
// rpe (validated R5, unchanged)
// ===========================================================================
__global__ void __launch_bounds__(256) rpe_kernel(
    const float* __restrict__ rawq, const float* __restrict__ relE)
{
    __shared__ __align__(16) float Rs[32][64];
    __shared__ __align__(16) float Es[32][128];

    const int tx = threadIdx.x;
    const int kt = blockIdx.x, qt = blockIdx.y, bh = blockIdx.z;
    const int b = bh >> 4, h = bh & 15;
    const int q0 = qt << 6, k0 = kt << 6;
    const int base = k0 - q0 + 999;
    const int tm = (tx >> 4) << 2;
    const int tn = (tx & 15) << 2;

    const float* Rb = rawq + ((size_t)(b * 1024 + q0)) * 1024 + h * 64;

    float acc[4][4];
#pragma unroll
    for (int i = 0; i < 4; i++)
#pragma unroll
        for (int j = 0; j < 4; j++) acc[i][j] = 0.f;

    for (int d0 = 0; d0 < 64; d0 += 32) {
        __syncthreads();
        for (int idx = tx; idx < 512; idx += 256) {
            const int qq = idx >> 3;
            const int c4 = (idx & 7) << 2;
            float4 rv = *(const float4*)(Rb + (size_t)qq * 1024 + d0 + c4);
            Rs[c4 + 0][qq] = rv.x; Rs[c4 + 1][qq] = rv.y;
            Rs[c4 + 2][qq] = rv.z; Rs[c4 + 3][qq] = rv.w;
        }
        for (int idx = tx; idx < 127 * 8; idx += 256) {
            const int ls = idx >> 3;
            const int c4 = (idx & 7) << 2;
            int j = base + ls - 63;
            j = j < 0 ? 0 : (j > 1998 ? 1998 : j);
            float4 ev = *(const float4*)(relE + (size_t)j * 64 + d0 + c4);
            Es[c4 + 0][ls] = ev.x; Es[c4 + 1][ls] = ev.y;
            Es[c4 + 2][ls] = ev.z; Es[c4 + 3][ls] = ev.w;
        }
        __syncthreads();

        const int eb = tn - tm + 60;
#pragma unroll 8
        for (int kk = 0; kk < 32; kk++) {
            float4 rv = *(const float4*)&Rs[kk][tm];
            const float* erow = &Es[kk][eb];
            float ra[4] = {rv.x, rv.y, rv.z, rv.w};
            float e[7];
#pragma unroll
            for (int t = 0; t < 7; t++) e[t] = erow[t];
#pragma unroll
            for (int i = 0; i < 4; i++)
#pragma unroll
                for (int j = 0; j < 4; j++)
                    acc[i][j] = fmaf(ra[i], e[j - i + 3], acc[i][j]);
        }
    }

    float* Sb = g_S + ((size_t)bh * 1024 + q0 + tm) * 1024 + k0 + tn;
#pragma unroll
    for (int i = 0; i < 4; i++) {
        float4 sv = *(const float4*)(Sb + (size_t)i * 1024);
        sv.x = (sv.x + acc[i][0]) * 8.0f;
        sv.y = (sv.y + acc[i][1]) * 8.0f;
        sv.z = (sv.z + acc[i][2]) * 8.0f;
        sv.w = (sv.w + acc[i][3]) * 8.0f;
        *(float4*)(Sb + (size_t)i * 1024) = sv;
    }
}

// ===========================================================================
// softmax (validated, unchanged)
// ===========================================================================
__global__ void __launch_bounds__(256) softmax_kernel(const void* __restrict__ mask)
{
    const int row = blockIdx.x;
    const int q = row & 1023;
    const int bh = row >> 10;
    const int b = bh >> 4;
    float* Srow = g_S + (size_t)row * 1024;
    const size_t mb = ((size_t)(b << 10) + q) * 1024;
    const int tx = threadIdx.x;
    const int k = tx << 2;

    const int fl = g_mask_flags;
    const int wdt = (fl & 1) ? 2 : ((fl & 2) ? 1 : 4);

    float4 sv = *(const float4*)(Srow + k);
    float v[4] = {sv.x, sv.y, sv.z, sv.w};
    const float NEG = __int_as_float(0xff800000);

    if (wdt == 4) {
        const unsigned int* mp = (const unsigned int*)mask + mb + k;
#pragma unroll
        for (int i = 0; i < 4; i++) if (mp[i]) v[i] = NEG;
    } else if (wdt == 2) {
        const unsigned short* mp = (const unsigned short*)mask + mb + k;
#pragma unroll
        for (int i = 0; i < 4; i++) if (mp[i]) v[i] = NEG;
    } else {
        const unsigned char* mp = (const unsigned char*)mask + mb + k;
#pragma unroll
        for (int i = 0; i < 4; i++) if (mp[i]) v[i] = NEG;
    }

    float mx = fmaxf(fmaxf(v[0], v[1]), fmaxf(v[2], v[3]));
#pragma unroll
    for (int off = 16; off; off >>= 1)
        mx = fmaxf(mx, __shfl_xor_sync(0xffffffffu, mx, off));
    __shared__ float red[8];
    if ((tx & 31) == 0) red[tx >> 5] = mx;
    __syncthreads();
    float rmax = red[0];
#pragma unroll
    for (int i = 1; i < 8; i++) rmax = fmaxf(rmax, red[i]);

    float e[4], s = 0.f;
#pragma unroll
    for (int i = 0; i < 4; i++) { e[i] = expf(v[i] - rmax); s += e[i]; }
#pragma unroll
    for (int off = 16; off; off >>= 1)
        s += __shfl_xor_sync(0xffffffffu, s, off);
    __syncthreads();
    if ((tx & 31) == 0) red[tx >> 5] = s;
    __syncthreads();
    float rs = 0.f;
#pragma unroll
    for (int i = 0; i < 8; i++) rs += red[i];
    const float inv = 1.0f / rs;

    *(float4*)(Srow + k) = make_float4(e[0] * inv, e[1] * inv, e[2] * inv, e[3] * inv);
}

// ===========================================================================
// av_mma (validated R5, unchanged)
// ===========================================================================
#define AV_SMEM_BYTES 98304

__global__ void __launch_bounds__(256, 1) av_mma_kernel()
{
    extern __shared__ __align__(16) uint32_t sm[];
    uint32_t* Ph = sm;
    uint32_t* Pl = sm + 8192;
    uint32_t* Vh = sm + 16384;
    uint32_t* Vl = sm + 20480;

    const int tid = threadIdx.x;
    const int wid = tid >> 5;
    const int lane = tid & 31;
    const int g = lane >> 2;
    const int tig = lane & 3;
    const int qt = blockIdx.x;
    const int bh = blockIdx.y;
    const int b = bh >> 4, h = bh & 15;
    const int q0 = qt << 7;

    float acc[8][4];
#pragma unroll
    for (int j = 0; j < 8; j++)
#pragma unroll
        for (int r = 0; r < 4; r++) acc[j][r] = 0.f;

    const int kp = tid >> 2;
    const int dq = (tid & 3) << 4;

#pragma unroll 1
    for (int kc = 0; kc < 8; kc++) {
        float4 pv[16];
#pragma unroll
        for (int i = 0; i < 16; i++) {
            const int fi = tid + (i << 8);
            const int prow = fi >> 5;
            const int pc4 = (fi & 31) << 2;
            pv[i] = *(const float4*)(g_S + ((size_t)bh * 1024 + q0 + prow) * 1024 +
                                     (kc << 7) + pc4);
        }
        float4 vv[8];
        {
            const size_t vb = (size_t)bh * 65536 + (size_t)((kc << 7) + (kp << 1)) * 64 + dq;
#pragma unroll
            for (int m = 0; m < 4; m++) {
                vv[m] = *(const float4*)(g_V + vb + (m << 2));
                vv[4 + m] = *(const float4*)(g_V + vb + 64 + (m << 2));
            }
        }
        __syncthreads();

#pragma unroll
        for (int i = 0; i < 16; i++) {
            const int fi = tid + (i << 8);
            const int prow = fi >> 5;
            const int pc4 = (fi & 31) << 2;
            uint32_t h0, l0, h1, l1;
            split2(pv[i].x, pv[i].y, h0, l0);
            split2(pv[i].z, pv[i].w, h1, l1);
            const int s0 = a_slot(prow, pc4), s1 = a_slot(prow, pc4 + 2);
            Ph[s0] = h0; Pl[s0] = l0; Ph[s1] = h1; Pl[s1] = l1;
        }
#pragma unroll
        for (int m = 0; m < 4; m++) {
            const float* v0 = (const float*)&vv[m];
            const float* v1 = (const float*)&vv[4 + m];
#pragma unroll
            for (int dd = 0; dd < 4; dd++) {
                uint32_t hi, lo;
                split2(v0[dd], v1[dd], hi, lo);
                const int slot = b_slotN(dq + (m << 2) + dd, kp << 1, 8);
                Vh[slot] = hi; Vl[slot] = lo;
            }
        }
        __syncthreads();

#pragma unroll
        for (int s = 0; s < 8; s++) {
            uint32_t ah[4], al[4];
            const int ai = (((s << 3) + wid) << 7) + (lane << 2);
            *(uint4*)ah = *(const uint4*)(Ph + ai);
            *(uint4*)al = *(const uint4*)(Pl + ai);
#pragma unroll
            for (int j = 0; j < 8; j++) {
                uint32_t bh2[2], bl2[2];
                const int bi = (((s << 3) + j) << 6) + (lane << 1);
                *(uint2*)bh2 = *(const uint2*)(Vh + bi);
                *(uint2*)bl2 = *(const uint2*)(Vl + bi);
                mma16816(acc[j], ah, bh2);
                mma16816(acc[j], ah, bl2);
                mma16816(acc[j], al, bh2);
            }
        }
    }

    const int qrow = q0 + (wid << 4) + g;
#pragma unroll
    for (int j = 0; j < 8; j++) {
        const int d = (j << 3) + (tig << 1);
        float* op = g_O + ((size_t)(b * 1024 + qrow)) * 1024 + h * 64 + d;
        *(float2*)op = make_float2(acc[j][0], acc[j][1]);
        *(float2*)(op + (size_t)8 * 1024) = make_float2(acc[j][2], acc[j][3]);
    }
}

// ===========================================================================
// Launch
// ===========================================================================
extern "C" void kernel_launch(void* const* d_in, const int* in_sizes, int n_in,
                              void* d_out, int out_size)
{
    const float* query = (const float*)d_in[0];
    const float* key_i = (const float*)d_in[1];
    const float* value = (const float*)d_in[2];
    const void*  mask  = d_in[3];
    const float* q_w = (const float*)d_in[4];
    const float* q_b = (const float*)d_in[5];
    const float* k_w = (const float*)d_in[6];
    const float* k_b = (const float*)d_in[7];
    const float* v_w = (const float*)d_in[8];
    const float* v_b = (const float*)d_in[9];
    const float* o_w = (const float*)d_in[10];
    const float* o_b = (const float*)d_in[11];
    const float* relE = (const float*)d_in[12];
    float* out = (float*)d_out;

    static int attr_set = 0;
    if (!attr_set) {
        cudaFuncSetAttribute(qk_mma_kernel,
                             cudaFuncAttributeMaxDynamicSharedMemorySize,
                             QK_SMEM_BYTES);
        cudaFuncSetAttribute(av_mma_kernel,
                             cudaFuncAttributeMaxDynamicSharedMemorySize,
                             AV_SMEM_BYTES);
        attr_set = 1;
    }

    dim3 gf(8, 32);   // (nb, rb)

    conv_a_kernel<<<8192, 256>>>(query, 0);
    conv_b_kernel<<<2048, 256>>>(q_w);
    gemm_frag_kernel<<<gf, 256>>>(q_b, nullptr, 0, 1);

    conv_a_kernel<<<8192, 256>>>(key_i, 0);
    conv_b_kernel<<<2048, 256>>>(k_w);
    gemm_frag_kernel<<<gf, 256>>>(k_b, nullptr, 1, 1);

    conv_a_kernel<<<8192, 256>>>(value, 0);
    conv_b_kernel<<<2048, 256>>>(v_w);
    gemm_frag_kernel<<<gf, 256>>>(v_b, nullptr, 2, 1);

    mask_detect_kernel<<<256, 256>>>((const unsigned int*)mask);

    qk_mma_kernel<<<dim3(8, 8, 64), 256, QK_SMEM_BYTES>>>();
    rpe_kernel<<<dim3(16, 16, 64), 256>>>(query, relE);
    softmax_kernel<<<65536, 256>>>(mask);
    av_mma_kernel<<<dim3(8, 64), 256, AV_SMEM_BYTES>>>();

    conv_a_kernel<<<8192, 256>>>(nullptr, 1);
    conv_b_kernel<<<2048, 256>>>(o_w);
    gemm_frag_kernel<<<gf, 256>>>(o_b, out, 3, 0);
}

// round 7
// speedup vs baseline: 2.2628x; 1.3155x over previous
#include <cuda_runtime.h>
#include <cuda_bf16.h>
#include <cstdint>
#include <cstddef>

#define BB 4
#define TT 1024
#define HH 16
#define DD 64
#define CC 1024
#define MM 4096

__device__ float g_Q[(size_t)BB * HH * TT * DD];
__device__ float g_K[(size_t)BB * HH * TT * DD];
__device__ float g_V[(size_t)BB * HH * TT * DD];
__device__ float g_S[(size_t)BB * HH * TT * TT];
__device__ float g_O[(size_t)MM * CC];
__device__ int   g_mask_flags;

// fragment-ordered bf16 planes (u32 = packed bf16x2)
__device__ uint32_t g_Ah[(size_t)MM * CC / 2];   // 8 MB
__device__ uint32_t g_Al[(size_t)MM * CC / 2];
__device__ uint32_t g_Wh[(size_t)CC * CC / 2];   // 2 MB
__device__ uint32_t g_Wl[(size_t)CC * CC / 2];

// rpe band-GEMM operands + result
__device__ uint32_t g_RQh[(size_t)64 * 8 * 4096];        // 8 MB (per bh,qt A tiles)
__device__ uint32_t g_RQl[(size_t)64 * 8 * 4096];
__device__ uint32_t g_Eh[(size_t)8 * 9 * 4 * 1024];      // 1.2 MB (per qt E bands)
__device__ uint32_t g_El[(size_t)8 * 9 * 4 * 1024];
__device__ float    g_G[(size_t)64 * 8 * 128 * 1152];    // 483 MB

// ===========================================================================
// shared helpers (validated R4-R6)
// ===========================================================================
__device__ __forceinline__ void mma16816(float* c, const uint32_t* a,
                                         const uint32_t* b) {
    asm volatile(
        "mma.sync.aligned.m16n8k16.row.col.f32.bf16.bf16.f32 "
        "{%0,%1,%2,%3}, {%4,%5,%6,%7}, {%8,%9}, {%0,%1,%2,%3};"
        : "+f"(c[0]), "+f"(c[1]), "+f"(c[2]), "+f"(c[3])
        : "r"(a[0]), "r"(a[1]), "r"(a[2]), "r"(a[3]), "r"(b[0]), "r"(b[1]));
}

__device__ __forceinline__ void split2(float x, float y, uint32_t& hi, uint32_t& lo) {
    __nv_bfloat16 hx = __float2bfloat16(x);
    __nv_bfloat16 hy = __float2bfloat16(y);
    __nv_bfloat16 lx = __float2bfloat16(x - __bfloat162float(hx));
    __nv_bfloat16 ly = __float2bfloat16(y - __bfloat162float(hy));
    hi = ((uint32_t)__bfloat16_as_ushort(hy) << 16) | __bfloat16_as_ushort(hx);
    lo = ((uint32_t)__bfloat16_as_ushort(ly) << 16) | __bfloat16_as_ushort(lx);
}

__device__ __forceinline__ int a_slot(int row, int k) {
    const int kstep = k >> 4, kk = k & 15;
    const int mt = row >> 4, rit = row & 15;
    const int lane = ((rit & 7) << 2) | ((kk >> 1) & 3);
    const int r = (rit >> 3) | (((kk >> 3) & 1) << 1);
    return (((kstep << 3) + mt) << 7) + (lane << 2) + r;
}
__device__ __forceinline__ int b_slotN(int n, int k, int NT) {
    const int kstep = k >> 4, kk = k & 15;
    const int nt = n >> 3, gc = n & 7;
    const int lane = (gc << 2) | ((kk >> 1) & 3);
    const int r = (kk >> 3) & 1;
    return (((kstep * NT) + nt) << 6) + (lane << 1) + r;
}

// ===========================================================================
// converters (conv_a/conv_b validated R6; conv_rq/conv_e mirror them)
// ===========================================================================
__global__ void __launch_bounds__(256) conv_a_kernel(const float* __restrict__ ext,
                                                     int srcsel)
{
    const float* src = srcsel ? g_O : ext;
    const uint32_t o = blockIdx.x * 256 + threadIdx.x;
    const uint32_t region = o >> 10;
    const uint32_t rb = region >> 6, ks = region & 63;
    const uint32_t ol = o & 1023;
    const uint32_t mt = ol >> 7;
    const uint32_t lane = (ol >> 2) & 31;
    const uint32_t r = ol & 3;
    const uint32_t rit = ((r & 1) << 3) | (lane >> 2);
    const uint32_t kk = ((r >> 1) << 3) | ((lane & 3) << 1);
    const uint32_t row = (rb << 7) + (mt << 4) + rit;
    const uint32_t k = (ks << 4) + kk;
    const float2 v = *(const float2*)(src + (size_t)row * 1024 + k);
    uint32_t hi, lo;
    split2(v.x, v.y, hi, lo);
    g_Ah[o] = hi;
    g_Al[o] = lo;
}

__global__ void __launch_bounds__(256) conv_b_kernel(const float* __restrict__ w)
{
    const uint32_t o = blockIdx.x * 256 + threadIdx.x;
    const uint32_t region = o >> 10;
    const uint32_t nb = region >> 6, ks = region & 63;
    const uint32_t ol = o & 1023;
    const uint32_t nt = ol >> 6;
    const uint32_t lane = (ol >> 1) & 31;
    const uint32_t r = ol & 1;
    const uint32_t gc = lane >> 2;
    const uint32_t kk = (r << 3) | ((lane & 3) << 1);
    const uint32_t n = (nb << 7) + (nt << 3) + gc;
    const uint32_t k = (ks << 4) + kk;
    const float2 v = *(const float2*)(w + (size_t)n * 1024 + k);
    uint32_t hi, lo;
    split2(v.x, v.y, hi, lo);
    g_Wh[o] = hi;
    g_Wl[o] = lo;
}

// rawq head-slices -> A-planes per (bh, qt). region = (bh*8+qt)*4 + ks
__global__ void __launch_bounds__(256) conv_rq_kernel(const float* __restrict__ q)
{
    const uint32_t o = blockIdx.x * 256 + threadIdx.x;     // 0 .. 2M-1
    const uint32_t region = o >> 10;
    const uint32_t bhqt = region >> 2, ks = region & 3;
    const uint32_t bh = bhqt >> 3, qt = bhqt & 7;
    const uint32_t b = bh >> 4, h = bh & 15;
    const uint32_t ol = o & 1023;
    const uint32_t mt = ol >> 7;
    const uint32_t lane = (ol >> 2) & 31;
    const uint32_t r = ol & 3;
    const uint32_t rit = ((r & 1) << 3) | (lane >> 2);
    const uint32_t kk = ((r >> 1) << 3) | ((lane & 3) << 1);
    const uint32_t row = (qt << 7) + (mt << 4) + rit;      // 0..1023
    const uint32_t k = (ks << 4) + kk;                     // 0..63
    const float2 v = *(const float2*)(q + ((size_t)(b * 1024 + row)) * 1024 +
                                      h * 64 + k);
    uint32_t hi, lo;
    split2(v.x, v.y, hi, lo);
    g_RQh[o] = hi;
    g_RQl[o] = lo;
}

// rel band -> B-planes per qt: n in [0,1152), j = clip(872 - qt*128 + n)
__global__ void __launch_bounds__(256) conv_e_kernel(const float* __restrict__ relE)
{
    const uint32_t o = blockIdx.x * 256 + threadIdx.x;     // 0 .. 294911
    const uint32_t qt = o / 36864;
    const uint32_t rem = o - qt * 36864;
    const uint32_t region = rem >> 10;                     // nb*4 + ks
    const uint32_t nb = region >> 2, ks = region & 3;
    const uint32_t ol = rem & 1023;
    const uint32_t nt = ol >> 6;
    const uint32_t lane = (ol >> 1) & 31;
    const uint32_t r = ol & 1;
    const uint32_t gc = lane >> 2;
    const uint32_t kk = (r << 3) | ((lane & 3) << 1);
    const uint32_t n = (nb << 7) + (nt << 3) + gc;         // 0..1151
    const uint32_t k = (ks << 4) + kk;                     // 0..63
    int j = 872 - (int)(qt << 7) + (int)n;
    j = j < 0 ? 0 : (j > 1998 ? 1998 : j);
    const float2 v = *(const float2*)(relE + (size_t)j * 64 + k);
    uint32_t hi, lo;
    split2(v.x, v.y, hi, lo);
    g_Eh[o] = hi;
    g_El[o] = lo;
}

// ===========================================================================
// fragment-direct projection GEMM (validated R6, unchanged)
// ===========================================================================
__global__ void __launch_bounds__(256, 2) gemm_frag_kernel(
    const float* __restrict__ bias, float* extDst, int dstsel, int headmode)
{
    const int tid = threadIdx.x;
    const int wid = tid >> 5;
    const int lane = tid & 31;
    const int wm = wid >> 2;
    const int wn = wid & 3;
    const int g = lane >> 2;
    const int tig = lane & 3;
    const int nb = blockIdx.x;
    const int rb = blockIdx.y;

    float* Cout = (dstsel == 0) ? g_Q : (dstsel == 1) ? g_K :
                  (dstsel == 2) ? g_V : extDst;

    float acc[4][4][4];
#pragma unroll
    for (int i = 0; i < 4; i++)
#pragma unroll
        for (int j = 0; j < 4; j++)
#pragma unroll
            for (int r = 0; r < 4; r++) acc[i][j][r] = 0.f;

#pragma unroll 1
    for (int ks = 0; ks < 64; ks++) {
        const size_t abase = (size_t)((((rb << 6) + ks) << 3) + (wm << 2)) * 128 +
                             (lane << 2);
        const size_t bbase = (size_t)((((nb << 6) + ks) << 4) + (wn << 2)) * 64 +
                             (lane << 1);
        uint4 ah[4], al[4];
        uint2 bh[4], bl[4];
#pragma unroll
        for (int i = 0; i < 4; i++) {
            ah[i] = *(const uint4*)(g_Ah + abase + (i << 7));
            al[i] = *(const uint4*)(g_Al + abase + (i << 7));
        }
#pragma unroll
        for (int j = 0; j < 4; j++) {
            bh[j] = *(const uint2*)(g_Wh + bbase + (j << 6));
            bl[j] = *(const uint2*)(g_Wl + bbase + (j << 6));
        }
#pragma unroll
        for (int i = 0; i < 4; i++)
#pragma unroll
            for (int j = 0; j < 4; j++) {
                mma16816(acc[i][j], (const uint32_t*)&ah[i], (const uint32_t*)&bh[j]);
                mma16816(acc[i][j], (const uint32_t*)&ah[i], (const uint32_t*)&bl[j]);
                mma16816(acc[i][j], (const uint32_t*)&al[i], (const uint32_t*)&bh[j]);
            }
    }

    const int bm = rb << 7;
    const int bn = nb << 7;
#pragma unroll
    for (int i = 0; i < 4; i++) {
        const int m0 = bm + (wm << 6) + (i << 4) + g;
#pragma unroll
        for (int j = 0; j < 4; j++) {
            const int n = bn + (wn << 5) + (j << 3) + (tig << 1);
            const float2 bv = *(const float2*)(bias + n);
#pragma unroll
            for (int half = 0; half < 2; half++) {
                const int m = m0 + (half << 3);
                float2 o;
                o.x = acc[i][j][half * 2 + 0] + bv.x;
                o.y = acc[i][j][half * 2 + 1] + bv.y;
                size_t idx;
                if (headmode) {
                    idx = (((size_t)((m >> 10) * 16 + (n >> 6)) * 1024 +
                            (size_t)(m & 1023)) << 6) + (n & 63);
                } else {
                    idx = (size_t)m * 1024 + n;
                }
                *(float2*)(Cout + idx) = o;
            }
        }
    }
}

// ===========================================================================
// G band GEMM: G[bh][qt] = RQ_tile(128x64) @ E_band(1152x64)^T, bf16x3
// grid (9 nb, 8 qt, 64 bh)
// ===========================================================================
__global__ void __launch_bounds__(256, 2) g_gemm_kernel()
{
    const int tid = threadIdx.x;
    const int wid = tid >> 5;
    const int lane = tid & 31;
    const int wm = wid >> 2;
    const int wn = wid & 3;
    const int g = lane >> 2;
    const int tig = lane & 3;
    const int nb = blockIdx.x;
    const int qt = blockIdx.y;
    const int bh = blockIdx.z;

    float acc[4][4][4];
#pragma unroll
    for (int i = 0; i < 4; i++)
#pragma unroll
        for (int j = 0; j < 4; j++)
#pragma unroll
            for (int r = 0; r < 4; r++) acc[i][j][r] = 0.f;

#pragma unroll
    for (int ks = 0; ks < 4; ks++) {
        const size_t abase = (size_t)(((((bh << 3) + qt) << 2) + ks) * 8 +
                                      (wm << 2)) * 128 + (lane << 2);
        const size_t bbase = (size_t)((((qt * 9 + nb) << 2) + ks) * 16 +
                                      (wn << 2)) * 64 + (lane << 1);
        uint4 ah[4], al[4];
        uint2 bh2[4], bl2[4];
#pragma unroll
        for (int i = 0; i < 4; i++) {
            ah[i] = *(const uint4*)(g_RQh + abase + (i << 7));
            al[i] = *(const uint4*)(g_RQl + abase + (i << 7));
        }
#pragma unroll
        for (int j = 0; j < 4; j++) {
            bh2[j] = *(const uint2*)(g_Eh + bbase + (j << 6));
            bl2[j] = *(const uint2*)(g_El + bbase + (j << 6));
        }
#pragma unroll
        for (int i = 0; i < 4; i++)
#pragma unroll
            for (int j = 0; j < 4; j++) {
                mma16816(acc[i][j], (const uint32_t*)&ah[i], (const uint32_t*)&bh2[j]);
                mma16816(acc[i][j], (const uint32_t*)&ah[i], (const uint32_t*)&bl2[j]);
                mma16816(acc[i][j], (const uint32_t*)&al[i], (const uint32_t*)&bh2[j]);
            }
    }

    float* Gb = g_G + (size_t)(((bh << 3) + qt) << 7) * 1152;
#pragma unroll
    for (int i = 0; i < 4; i++) {
        const int m0 = (wm << 6) + (i << 4) + g;
#pragma unroll
        for (int j = 0; j < 4; j++) {
            const int n = (nb << 7) + (wn << 5) + (j << 3) + (tig << 1);
#pragma unroll
            for (int half = 0; half < 2; half++) {
                const int m = m0 + (half << 3);
                *(float2*)(Gb + (size_t)m * 1152 + n) =
                    make_float2(acc[i][j][half * 2 + 0], acc[i][j][half * 2 + 1]);
            }
        }
    }
}

// ===========================================================================
// mask dtype-width detector (validated)
// ===========================================================================
__global__ void mask_detect_kernel(const unsigned int* __restrict__ m) {
    unsigned f = 0;
    for (unsigned i = blockIdx.x * blockDim.x + threadIdx.x; i < (1u << 20);
         i += blockDim.x * gridDim.x) {
        unsigned w = m[i];
        if (w == 0u) continue;
        unsigned lo = w & 0xFFFFu;
        if (lo == 0x3F80u || lo == 0x3C00u) f |= 1u;
        if (((w & 0xFEFEFEFEu) == 0u) && w > 1u) f |= 2u;
    }
    if (f) atomicOr(&g_mask_flags, (int)f);
}

// ===========================================================================
// qk_mma (validated R5/R6, unchanged — stores RAW QK)
// ===========================================================================
#define QK_SMEM_BYTES 67584

__global__ void __launch_bounds__(256, 1) qk_mma_kernel()
{
    extern __shared__ __align__(16) uint32_t sm[];
    const int tid = threadIdx.x;
    const int wid = tid >> 5;
    const int lane = tid & 31;
    const int g = lane >> 2;
    const int tig = lane & 3;
    const int kt = blockIdx.x, qt = blockIdx.y, bh = blockIdx.z;
    const int q0 = qt << 7, k0 = kt << 7;

    uint32_t* Qh = sm;
    uint32_t* Ql = sm + 4096;
    uint32_t* Kh = sm + 8192;
    uint32_t* Kl = sm + 12288;

    {
        const int row = tid >> 1;
        const int d0 = (tid & 1) << 5;
        const float* qs = g_Q + ((size_t)bh * 1024 + q0 + row) * 64 + d0;
        const float* ks = g_K + ((size_t)bh * 1024 + k0 + row) * 64 + d0;
#pragma unroll
        for (int qi = 0; qi < 8; qi++) {
            const int kq = d0 + (qi << 2);
            float4 v = *(const float4*)(qs + (qi << 2));
            uint32_t h0, l0, h1, l1;
            split2(v.x, v.y, h0, l0);
            split2(v.z, v.w, h1, l1);
            int s0 = a_slot(row, kq), s1 = a_slot(row, kq + 2);
            Qh[s0] = h0; Ql[s0] = l0; Qh[s1] = h1; Ql[s1] = l1;
            v = *(const float4*)(ks + (qi << 2));
            split2(v.x, v.y, h0, l0);
            split2(v.z, v.w, h1, l1);
            s0 = b_slotN(row, kq, 16); s1 = b_slotN(row, kq + 2, 16);
            Kh[s0] = h0; Kl[s0] = l0; Kh[s1] = h1; Kl[s1] = l1;
        }
    }
    __syncthreads();

    float acc[16][4];
#pragma unroll
    for (int j = 0; j < 16; j++)
#pragma unroll
        for (int r = 0; r < 4; r++) acc[j][r] = 0.f;

    uint32_t ah[4][4], al[4][4];
#pragma unroll
    for (int s = 0; s < 4; s++) {
        const int ai = (((s << 3) + wid) << 7) + (lane << 2);
        *(uint4*)ah[s] = *(const uint4*)(Qh + ai);
        *(uint4*)al[s] = *(const uint4*)(Ql + ai);
    }
#pragma unroll
    for (int j = 0; j < 16; j++) {
#pragma unroll
        for (int s = 0; s < 4; s++) {
            uint32_t bh2[2], bl2[2];
            const int bi = (((s << 4) + j) << 6) + (lane << 1);
            *(uint2*)bh2 = *(const uint2*)(Kh + bi);
            *(uint2*)bl2 = *(const uint2*)(Kl + bi);
            mma16816(acc[j], ah[s], bh2);
            mma16816(acc[j], ah[s], bl2);
            mma16816(acc[j], al[s], bh2);
        }
    }
    __syncthreads();

    float* stg = (float*)sm;
    {
        const int r0 = (wid << 4) + g;
#pragma unroll
        for (int j = 0; j < 16; j++) {
            const int col = (j << 3) + (tig << 1);
            *(float2*)&stg[r0 * 132 + col] = make_float2(acc[j][0], acc[j][1]);
            *(float2*)&stg[(r0 + 8) * 132 + col] = make_float2(acc[j][2], acc[j][3]);
        }
    }
    __syncthreads();

    float* Sb = g_S + ((size_t)bh << 20) + (size_t)q0 * 1024 + k0;
#pragma unroll
    for (int i = 0; i < 16; i++) {
        const int fi = tid + (i << 8);
        const int row = fi >> 5;
        const int c4 = (fi & 31) << 2;
        *(float4*)(Sb + (size_t)row * 1024 + c4) = *(const float4*)&stg[row * 132 + c4];
    }
}

// ===========================================================================
// fused softmax: v = (S + G_gathered) * 8, mask, softmax
// ===========================================================================
__global__ void __launch_bounds__(256) softmax_kernel(const void* __restrict__ mask)
{
    const int row = blockIdx.x;
    const int q = row & 1023;
    const int bh = row >> 10;
    const int b = bh >> 4;
    float* Srow = g_S + (size_t)row * 1024;
    const size_t mb = ((size_t)(b << 10) + q) * 1024;
    const int tx = threadIdx.x;
    const int k = tx << 2;

    const int fl = g_mask_flags;
    const int wdt = (fl & 1) ? 2 : ((fl & 2) ? 1 : 4);

    const int qi = q & 127;
    const int qt = q >> 7;
    const float* Gp = g_G + ((size_t)(((bh << 3) + qt) << 7) + qi) * 1152 +
                      (127 - qi) + k;

    float4 sv = *(const float4*)(Srow + k);
    float v[4];
    v[0] = (sv.x + Gp[0]) * 8.0f;
    v[1] = (sv.y + Gp[1]) * 8.0f;
    v[2] = (sv.z + Gp[2]) * 8.0f;
    v[3] = (sv.w + Gp[3]) * 8.0f;
    const float NEG = __int_as_float(0xff800000);

    if (wdt == 4) {
        const unsigned int* mp = (const unsigned int*)mask + mb + k;
#pragma unroll
        for (int i = 0; i < 4; i++) if (mp[i]) v[i] = NEG;
    } else if (wdt == 2) {
        const unsigned short* mp = (const unsigned short*)mask + mb + k;
#pragma unroll
        for (int i = 0; i < 4; i++) if (mp[i]) v[i] = NEG;
    } else {
        const unsigned char* mp = (const unsigned char*)mask + mb + k;
#pragma unroll
        for (int i = 0; i < 4; i++) if (mp[i]) v[i] = NEG;
    }

    float mx = fmaxf(fmaxf(v[0], v[1]), fmaxf(v[2], v[3]));
#pragma unroll
    for (int off = 16; off; off >>= 1)
        mx = fmaxf(mx, __shfl_xor_sync(0xffffffffu, mx, off));
    __shared__ float red[8];
    if ((tx & 31) == 0) red[tx >> 5] = mx;
    __syncthreads();
    float rmax = red[0];
#pragma unroll
    for (int i = 1; i < 8; i++) rmax = fmaxf(rmax, red[i]);

    float e[4], s = 0.f;
#pragma unroll
    for (int i = 0; i < 4; i++) { e[i] = expf(v[i] - rmax); s += e[i]; }
#pragma unroll
    for (int off = 16; off; off >>= 1)
        s += __shfl_xor_sync(0xffffffffu, s, off);
    __syncthreads();
    if ((tx & 31) == 0) red[tx >> 5] = s;
    __syncthreads();
    float rs = 0.f;
#pragma unroll
    for (int i = 0; i < 8; i++) rs += red[i];
    const float inv = 1.0f / rs;

    *(float4*)(Srow + k) = make_float4(e[0] * inv, e[1] * inv, e[2] * inv, e[3] * inv);
}

// ===========================================================================
// av_mma (validated R5/R6, unchanged)
// ===========================================================================
#define AV_SMEM_BYTES 98304

__global__ void __launch_bounds__(256, 1) av_mma_kernel()
{
    extern __shared__ __align__(16) uint32_t sm[];
    uint32_t* Ph = sm;
    uint32_t* Pl = sm + 8192;
    uint32_t* Vh = sm + 16384;
    uint32_t* Vl = sm + 20480;

    const int tid = threadIdx.x;
    const int wid = tid >> 5;
    const int lane = tid & 31;
    const int g = lane >> 2;
    const int tig = lane & 3;
    const int qt = blockIdx.x;
    const int bh = blockIdx.y;
    const int b = bh >> 4, h = bh & 15;
    const int q0 = qt << 7;

    float acc[8][4];
#pragma unroll
    for (int j = 0; j < 8; j++)
#pragma unroll
        for (int r = 0; r < 4; r++) acc[j][r] = 0.f;

    const int kp = tid >> 2;
    const int dq = (tid & 3) << 4;

#pragma unroll 1
    for (int kc = 0; kc < 8; kc++) {
        float4 pv[16];
#pragma unroll
        for (int i = 0; i < 16; i++) {
            const int fi = tid + (i << 8);
            const int prow = fi >> 5;
            const int pc4 = (fi & 31) << 2;
            pv[i] = *(const float4*)(g_S + ((size_t)bh * 1024 + q0 + prow) * 1024 +
                                     (kc << 7) + pc4);
        }
        float4 vv[8];
        {
            const size_t vb = (size_t)bh * 65536 + (size_t)((kc << 7) + (kp << 1)) * 64 + dq;
#pragma unroll
            for (int m = 0; m < 4; m++) {
                vv[m] = *(const float4*)(g_V + vb + (m << 2));
                vv[4 + m] = *(const float4*)(g_V + vb + 64 + (m << 2));
            }
        }
        __syncthreads();

#pragma unroll
        for (int i = 0; i < 16; i++) {
            const int fi = tid + (i << 8);
            const int prow = fi >> 5;
            const int pc4 = (fi & 31) << 2;
            uint32_t h0, l0, h1, l1;
            split2(pv[i].x, pv[i].y, h0, l0);
            split2(pv[i].z, pv[i].w, h1, l1);
            const int s0 = a_slot(prow, pc4), s1 = a_slot(prow, pc4 + 2);
            Ph[s0] = h0; Pl[s0] = l0; Ph[s1] = h1; Pl[s1] = l1;
        }
#pragma unroll
        for (int m = 0; m < 4; m++) {
            const float* v0 = (const float*)&vv[m];
            const float* v1 = (const float*)&vv[4 + m];
#pragma unroll
            for (int dd = 0; dd < 4; dd++) {
                uint32_t hi, lo;
                split2(v0[dd], v1[dd], hi, lo);
                const int slot = b_slotN(dq + (m << 2) + dd, kp << 1, 8);
                Vh[slot] = hi; Vl[slot] = lo;
            }
        }
        __syncthreads();

#pragma unroll
        for (int s = 0; s < 8; s++) {
            uint32_t ah[4], al[4];
            const int ai = (((s << 3) + wid) << 7) + (lane << 2);
            *(uint4*)ah = *(const uint4*)(Ph + ai);
            *(uint4*)al = *(const uint4*)(Pl + ai);
#pragma unroll
            for (int j = 0; j < 8; j++) {
                uint32_t bh2[2], bl2[2];
                const int bi = (((s << 3) + j) << 6) + (lane << 1);
                *(uint2*)bh2 = *(const uint2*)(Vh + bi);
                *(uint2*)bl2 = *(const uint2*)(Vl + bi);
                mma16816(acc[j], ah, bh2);
                mma16816(acc[j], ah, bl2);
                mma16816(acc[j], al, bh2);
            }
        }
    }

    const int qrow = q0 + (wid << 4) + g;
#pragma unroll
    for (int j = 0; j < 8; j++) {
        const int d = (j << 3) + (tig << 1);
        float* op = g_O + ((size_t)(b * 1024 + qrow)) * 1024 + h * 64 + d;
        *(float2*)op = make_float2(acc[j][0], acc[j][1]);
        *(float2*)(op + (size_t)8 * 1024) = make_float2(acc[j][2], acc[j][3]);
    }
}

// ===========================================================================
// Launch
// ===========================================================================
extern "C" void kernel_launch(void* const* d_in, const int* in_sizes, int n_in,
                              void* d_out, int out_size)
{
    const float* query = (const float*)d_in[0];
    const float* key_i = (const float*)d_in[1];
    const float* value = (const float*)d_in[2];
    const void*  mask  = d_in[3];
    const float* q_w = (const float*)d_in[4];
    const float* q_b = (const float*)d_in[5];
    const float* k_w = (const float*)d_in[6];
    const float* k_b = (const float*)d_in[7];
    const float* v_w = (const float*)d_in[8];
    const float* v_b = (const float*)d_in[9];
    const float* o_w = (const float*)d_in[10];
    const float* o_b = (const float*)d_in[11];
    const float* relE = (const float*)d_in[12];
    float* out = (float*)d_out;

    static int attr_set = 0;
    if (!attr_set) {
        cudaFuncSetAttribute(qk_mma_kernel,
                             cudaFuncAttributeMaxDynamicSharedMemorySize,
                             QK_SMEM_BYTES);
        cudaFuncSetAttribute(av_mma_kernel,
                             cudaFuncAttributeMaxDynamicSharedMemorySize,
                             AV_SMEM_BYTES);
        attr_set = 1;
    }

    dim3 gf(8, 32);

    conv_a_kernel<<<8192, 256>>>(query, 0);
    conv_b_kernel<<<2048, 256>>>(q_w);
    gemm_frag_kernel<<<gf, 256>>>(q_b, nullptr, 0, 1);

    conv_a_kernel<<<8192, 256>>>(key_i, 0);
    conv_b_kernel<<<2048, 256>>>(k_w);
    gemm_frag_kernel<<<gf, 256>>>(k_b, nullptr, 1, 1);

    conv_a_kernel<<<8192, 256>>>(value, 0);
    conv_b_kernel<<<2048, 256>>>(v_w);
    gemm_frag_kernel<<<gf, 256>>>(v_b, nullptr, 2, 1);

    // rpe band-GEMM operands + G
    conv_rq_kernel<<<8192, 256>>>(query);
    conv_e_kernel<<<1152, 256>>>(relE);
    g_gemm_kernel<<<dim3(9, 8, 64), 256>>>();

    mask_detect_kernel<<<256, 256>>>((const unsigned int*)mask);

    qk_mma_kernel<<<dim3(8, 8, 64), 256, QK_SMEM_BYTES>>>();
    softmax_kernel<<<65536, 256>>>(mask);
    av_mma_kernel<<<dim3(8, 64), 256, AV_SMEM_BYTES>>>();

    conv_a_kernel<<<8192, 256>>>(nullptr, 1);
    conv_b_kernel<<<2048, 256>>>(o_w);
    gemm_frag_kernel<<<gf, 256>>>(o_b, out, 3, 0);
}